// round 15
// baseline (speedup 1.0000x reference)
#include <cuda_runtime.h>
#include <cuda_bf16.h>
#include <cstdint>

#define NHEAD 4
#define NEG_SLOPE 0.2f

// ---------------- scratch (allocation-free: __device__ globals) ----------------
__device__ __nv_bfloat16 g_yh  [11264 * 1024];   // layer-0 aggregates, bf16 hi
__device__ __nv_bfloat16 g_yl  [11264 * 1024];   // layer-0 aggregates, bf16 lo
__device__ float         g_h   [11264 * 512];    // layer-0 outputs (f32)
__device__ __nv_bfloat16 g_y2h [1024 * 2048];    // layer-1 aggregates hi
__device__ __nv_bfloat16 g_y2l [1024 * 2048];    // layer-1 aggregates lo
__device__ float         g_W2  [NHEAD * 512 * 256];   // folded weights (f32)
__device__ __nv_bfloat16 g_Wt2h[NHEAD * 256 * 512];   // W2 transposed+split
__device__ __nv_bfloat16 g_Wt2l[NHEAD * 256 * 512];
__device__ __nv_bfloat16 g_Wt0h[NHEAD * 128 * 256];   // w0 transposed+split
__device__ __nv_bfloat16 g_Wt0l[NHEAD * 128 * 256];
__device__ float         g_part[8 * 1024 * 256];      // per-(head,ksplit) partial outputs

// ---------------- helpers ----------------
__device__ __forceinline__ uint32_t smem_u32(const void* p) {
    uint32_t a;
    asm("{ .reg .u64 t; cvta.to.shared.u64 t, %1; cvt.u32.u64 %0, t; }" : "=r"(a) : "l"(p));
    return a;
}
#define CP16(d, s)  asm volatile("cp.async.cg.shared.global [%0], [%1], 16;" :: "r"(d), "l"(s))
#define CP_COMMIT() asm volatile("cp.async.commit_group;" ::: "memory")
#define CP_WAIT0()  asm volatile("cp.async.wait_group 0;" ::: "memory")

__device__ __forceinline__ uint32_t bfsplit2(float v0, float v1, uint32_t& lopk) {
    const unsigned short h0 = __bfloat16_as_ushort(__float2bfloat16_rn(v0));
    const unsigned short h1 = __bfloat16_as_ushort(__float2bfloat16_rn(v1));
    const float r0 = v0 - __bfloat162float(__ushort_as_bfloat16(h0));
    const float r1 = v1 - __bfloat162float(__ushort_as_bfloat16(h1));
    const unsigned short l0 = __bfloat16_as_ushort(__float2bfloat16_rn(r0));
    const unsigned short l1 = __bfloat16_as_ushort(__float2bfloat16_rn(r1));
    lopk = (uint32_t)l0 | ((uint32_t)l1 << 16);
    return (uint32_t)h0 | ((uint32_t)h1 << 16);
}

__device__ __forceinline__ void mma_bf16(float* d, const uint32_t* a, const uint32_t* b) {
    asm volatile(
        "mma.sync.aligned.m16n8k16.row.col.f32.bf16.bf16.f32 "
        "{%0,%1,%2,%3}, {%4,%5,%6,%7}, {%8,%9}, {%0,%1,%2,%3};"
        : "+f"(d[0]), "+f"(d[1]), "+f"(d[2]), "+f"(d[3])
        : "r"(a[0]), "r"(a[1]), "r"(a[2]), "r"(a[3]), "r"(b[0]), "r"(b[1]));
}

#define LRow 72

// ---------------- f32-input split-bf16 HMMA GEMM (fold only; proven) ----------------
__global__ __launch_bounds__(256)
void gemm_hmma(const float* __restrict__ A, const float* __restrict__ W,
               float* __restrict__ C,
               int K, int lda, long aHeadStride,
               int ldw, long wHeadStride,
               int ldc, long cHeadStride)
{
    extern __shared__ unsigned short smem[];
    unsigned short* AsH = smem;
    unsigned short* AsL = smem + 64 * LRow;
    unsigned short* BsH = smem + 2 * 64 * LRow;
    unsigned short* BsL = BsH + 128 * LRow;

    const int tid  = threadIdx.x;
    const int wid  = tid >> 5;
    const int lane = tid & 31;
    const int g    = lane >> 2;
    const int t    = lane & 3;
    const int wm   = (wid >> 2) * 32;
    const int wn   = (wid & 3) * 32;

    const int m0 = blockIdx.x * 64;
    const int bn = blockIdx.y * 128;
    const int h  = blockIdx.z;
    const float* Ah = A + (long)h * aHeadStride;
    const float* Wh = W + (long)h * wHeadStride;
    float*       Ch = C + (long)h * cHeadStride;

    float acc[2][4][4];
    #pragma unroll
    for (int i = 0; i < 2; i++)
        #pragma unroll
        for (int j = 0; j < 4; j++)
            #pragma unroll
            for (int q = 0; q < 4; q++) acc[i][j][q] = 0.f;

    const int nChunks = K >> 6;
    for (int s = 0; s < nChunks; s++) {
        const int k0 = s * 64;
        __syncthreads();

        #pragma unroll
        for (int i = 0; i < 4; i++) {
            const int idx = tid + i * 256;
            const int row = idx >> 4;
            const int c4  = (idx & 15) * 4;
            const float4 v = *(const float4*)(Ah + (long)(m0 + row) * lda + k0 + c4);
            uint32_t lo0, lo1;
            const uint32_t hi0 = bfsplit2(v.x, v.y, lo0);
            const uint32_t hi1 = bfsplit2(v.z, v.w, lo1);
            *(uint2*)&AsH[row * LRow + c4] = make_uint2(hi0, hi1);
            *(uint2*)&AsL[row * LRow + c4] = make_uint2(lo0, lo1);
        }
        {
            const int n  = tid & 127;
            const int kb = (tid >> 7) * 32;
            #pragma unroll
            for (int jq = 0; jq < 4; jq++) {
                uint32_t hi[4], lo[4];
                #pragma unroll
                for (int j2 = 0; j2 < 4; j2++) {
                    const int k = k0 + kb + jq * 8 + j2 * 2;
                    const float v0 = Wh[(long)k * ldw + bn + n];
                    const float v1 = Wh[(long)(k + 1) * ldw + bn + n];
                    hi[j2] = bfsplit2(v0, v1, lo[j2]);
                }
                *(uint4*)&BsH[n * LRow + kb + jq * 8] = make_uint4(hi[0], hi[1], hi[2], hi[3]);
                *(uint4*)&BsL[n * LRow + kb + jq * 8] = make_uint4(lo[0], lo[1], lo[2], lo[3]);
            }
        }
        __syncthreads();

        #pragma unroll
        for (int kk = 0; kk < 64; kk += 16) {
            uint32_t ah[2][4], al[2][4];
            #pragma unroll
            for (int mt = 0; mt < 2; mt++) {
                const int r = wm + mt * 16;
                const int ca = kk + t * 2;
                ah[mt][0] = *(const uint32_t*)&AsH[(r + g)     * LRow + ca];
                ah[mt][1] = *(const uint32_t*)&AsH[(r + 8 + g) * LRow + ca];
                ah[mt][2] = *(const uint32_t*)&AsH[(r + g)     * LRow + ca + 8];
                ah[mt][3] = *(const uint32_t*)&AsH[(r + 8 + g) * LRow + ca + 8];
                al[mt][0] = *(const uint32_t*)&AsL[(r + g)     * LRow + ca];
                al[mt][1] = *(const uint32_t*)&AsL[(r + 8 + g) * LRow + ca];
                al[mt][2] = *(const uint32_t*)&AsL[(r + g)     * LRow + ca + 8];
                al[mt][3] = *(const uint32_t*)&AsL[(r + 8 + g) * LRow + ca + 8];
            }
            uint32_t bh[4][2], bl[4][2];
            #pragma unroll
            for (int nt = 0; nt < 4; nt++) {
                const int n = wn + nt * 8 + g;
                const int cb = kk + t * 2;
                bh[nt][0] = *(const uint32_t*)&BsH[n * LRow + cb];
                bh[nt][1] = *(const uint32_t*)&BsH[n * LRow + cb + 8];
                bl[nt][0] = *(const uint32_t*)&BsL[n * LRow + cb];
                bl[nt][1] = *(const uint32_t*)&BsL[n * LRow + cb + 8];
            }
            #pragma unroll
            for (int mt = 0; mt < 2; mt++)
                #pragma unroll
                for (int nt = 0; nt < 4; nt++) {
                    mma_bf16(acc[mt][nt], ah[mt], bh[nt]);
                    mma_bf16(acc[mt][nt], ah[mt], bl[nt]);
                    mma_bf16(acc[mt][nt], al[mt], bh[nt]);
                }
        }
    }

    #pragma unroll
    for (int mt = 0; mt < 2; mt++)
        #pragma unroll
        for (int nt = 0; nt < 4; nt++) {
            const int r  = m0 + wm + mt * 16 + g;
            const int cc = bn + wn + nt * 8 + t * 2;
            *(float2*)(Ch + (long)r * ldc + cc)       = make_float2(acc[mt][nt][0], acc[mt][nt][1]);
            *(float2*)(Ch + (long)(r + 8) * ldc + cc) = make_float2(acc[mt][nt][2], acc[mt][nt][3]);
        }
}

// ---------------- pre-split bf16 HMMA GEMM, register prefetch + split-K (proven) ----------------
__global__ __launch_bounds__(256)
void gemm_hmma_pre(const __nv_bfloat16* __restrict__ Ahg, const __nv_bfloat16* __restrict__ Alg,
                   const __nv_bfloat16* __restrict__ Whg, const __nv_bfloat16* __restrict__ Wlg,
                   float* __restrict__ C,
                   int kLen, int kStride, int nSplit,
                   int lda, long aHeadStride, long wHeadStride,
                   int ldc, long cSegStride)
{
    extern __shared__ unsigned short smem[];
    unsigned short* AsH = smem;
    unsigned short* AsL = smem + 64 * LRow;
    unsigned short* BsH = smem + 2 * 64 * LRow;
    unsigned short* BsL = BsH + 128 * LRow;

    const int tid  = threadIdx.x;
    const int wid  = tid >> 5;
    const int lane = tid & 31;
    const int g    = lane >> 2;
    const int t    = lane & 3;
    const int wm   = (wid >> 2) * 32;
    const int wn   = (wid & 3) * 32;

    const int m0 = blockIdx.x * 64;
    const int bn = blockIdx.y * 128;
    const int z  = blockIdx.z;
    const int h  = z / nSplit;
    const int kOff = (z % nSplit) * kLen;

    const unsigned short* pAh = (const unsigned short*)Ahg + (long)h * aHeadStride + kOff;
    const unsigned short* pAl = (const unsigned short*)Alg + (long)h * aHeadStride + kOff;
    const unsigned short* pWh = (const unsigned short*)Whg + (long)h * wHeadStride + (long)bn * kStride + kOff;
    const unsigned short* pWl = (const unsigned short*)Wlg + (long)h * wHeadStride + (long)bn * kStride + kOff;
    float* Ch = C + (long)z * cSegStride;

    float acc[2][4][4];
    #pragma unroll
    for (int i = 0; i < 2; i++)
        #pragma unroll
        for (int j = 0; j < 4; j++)
            #pragma unroll
            for (int q = 0; q < 4; q++) acc[i][j][q] = 0.f;

    const int arow = tid >> 3, ac8 = (tid & 7) * 8;
    const int brow = tid >> 3, bc8 = (tid & 7) * 8;

    uint4 ra[2], rl[2], rb[4], rbl[4];

    auto ldg = [&](int k0) {
        #pragma unroll
        for (int i = 0; i < 2; i++) {
            const long off = (long)(m0 + arow + i * 32) * lda + k0 + ac8;
            ra[i] = *(const uint4*)(pAh + off);
            rl[i] = *(const uint4*)(pAl + off);
        }
        #pragma unroll
        for (int i = 0; i < 4; i++) {
            const long off = (long)(brow + i * 32) * kStride + k0 + bc8;
            rb[i]  = *(const uint4*)(pWh + off);
            rbl[i] = *(const uint4*)(pWl + off);
        }
    };
    auto sts = [&]() {
        #pragma unroll
        for (int i = 0; i < 2; i++) {
            const int o = (arow + i * 32) * LRow + ac8;
            *(uint2*)&AsH[o]     = make_uint2(ra[i].x, ra[i].y);
            *(uint2*)&AsH[o + 4] = make_uint2(ra[i].z, ra[i].w);
            *(uint2*)&AsL[o]     = make_uint2(rl[i].x, rl[i].y);
            *(uint2*)&AsL[o + 4] = make_uint2(rl[i].z, rl[i].w);
        }
        #pragma unroll
        for (int i = 0; i < 4; i++) {
            const int o = (brow + i * 32) * LRow + bc8;
            *(uint2*)&BsH[o]     = make_uint2(rb[i].x, rb[i].y);
            *(uint2*)&BsH[o + 4] = make_uint2(rb[i].z, rb[i].w);
            *(uint2*)&BsL[o]     = make_uint2(rbl[i].x, rbl[i].y);
            *(uint2*)&BsL[o + 4] = make_uint2(rbl[i].z, rbl[i].w);
        }
    };
    auto compute = [&]() {
        #pragma unroll
        for (int kk = 0; kk < 64; kk += 16) {
            uint32_t ah[2][4], al[2][4];
            #pragma unroll
            for (int mt = 0; mt < 2; mt++) {
                const int r = wm + mt * 16;
                const int ca = kk + t * 2;
                ah[mt][0] = *(const uint32_t*)&AsH[(r + g)     * LRow + ca];
                ah[mt][1] = *(const uint32_t*)&AsH[(r + 8 + g) * LRow + ca];
                ah[mt][2] = *(const uint32_t*)&AsH[(r + g)     * LRow + ca + 8];
                ah[mt][3] = *(const uint32_t*)&AsH[(r + 8 + g) * LRow + ca + 8];
                al[mt][0] = *(const uint32_t*)&AsL[(r + g)     * LRow + ca];
                al[mt][1] = *(const uint32_t*)&AsL[(r + 8 + g) * LRow + ca];
                al[mt][2] = *(const uint32_t*)&AsL[(r + g)     * LRow + ca + 8];
                al[mt][3] = *(const uint32_t*)&AsL[(r + 8 + g) * LRow + ca + 8];
            }
            uint32_t bh[4][2], bl[4][2];
            #pragma unroll
            for (int nt = 0; nt < 4; nt++) {
                const int n = wn + nt * 8 + g;
                const int cb = kk + t * 2;
                bh[nt][0] = *(const uint32_t*)&BsH[n * LRow + cb];
                bh[nt][1] = *(const uint32_t*)&BsH[n * LRow + cb + 8];
                bl[nt][0] = *(const uint32_t*)&BsL[n * LRow + cb];
                bl[nt][1] = *(const uint32_t*)&BsL[n * LRow + cb + 8];
            }
            #pragma unroll
            for (int mt = 0; mt < 2; mt++)
                #pragma unroll
                for (int nt = 0; nt < 4; nt++) {
                    mma_bf16(acc[mt][nt], ah[mt], bh[nt]);
                    mma_bf16(acc[mt][nt], ah[mt], bl[nt]);
                    mma_bf16(acc[mt][nt], al[mt], bh[nt]);
                }
        }
    };

    const int nChunks = kLen >> 6;
    ldg(0);
    sts();
    __syncthreads();
    for (int s = 0; s < nChunks; s++) {
        if (s + 1 < nChunks) ldg((s + 1) * 64);
        compute();
        if (s + 1 < nChunks) {
            __syncthreads();
            sts();
            __syncthreads();
        }
    }

    #pragma unroll
    for (int mt = 0; mt < 2; mt++)
        #pragma unroll
        for (int nt = 0; nt < 4; nt++) {
            const int r  = m0 + wm + mt * 16 + g;
            const int cc = bn + wn + nt * 8 + t * 2;
            *(float2*)(Ch + (long)r * ldc + cc)       = make_float2(acc[mt][nt][0], acc[mt][nt][1]);
            *(float2*)(Ch + (long)(r + 8) * ldc + cc) = make_float2(acc[mt][nt][2], acc[mt][nt][3]);
        }
}

// ---------------- tiled transpose + split ----------------
__global__ void transpose_split(const float* __restrict__ in,
                                __nv_bfloat16* __restrict__ outh,
                                __nv_bfloat16* __restrict__ outl,
                                int K, int N)
{
    __shared__ float tile[32][33];
    const int h  = blockIdx.z;
    const int k0 = blockIdx.x * 32;
    const int n0 = blockIdx.y * 32;
    const int tx = threadIdx.x, ty = threadIdx.y;
    const float* ph = in + (long)h * K * N;

    #pragma unroll
    for (int j = 0; j < 32; j += 8)
        tile[ty + j][tx] = ph[(long)(k0 + ty + j) * N + n0 + tx];
    __syncthreads();

    const long ob = (long)h * N * K;
    #pragma unroll
    for (int j = 0; j < 32; j += 8) {
        const float v = tile[tx][ty + j];
        const __nv_bfloat16 hv = __float2bfloat16_rn(v);
        const long o = ob + (long)(n0 + ty + j) * K + k0 + tx;
        outh[o] = hv;
        outl[o] = __float2bfloat16_rn(v - __bfloat162float(hv));
    }
}

// ---------------- F=256 attention: smem-free 2-pass (global + L2), 128 threads ----------------
__global__ void __launch_bounds__(128, 8)
gat_attn256(const float* __restrict__ xsA, const float* __restrict__ xnA, int SA, int nA,
            const float* __restrict__ xsB, const float* __restrict__ xnB, int SB,
            const float* __restrict__ a_self, const float* __restrict__ a_neigh,
            __nv_bfloat16* __restrict__ yh, __nv_bfloat16* __restrict__ yl)
{
    __shared__ float slog[26 * 4];
    __shared__ float slself[4];

    const int tid = threadIdx.x;
    const int w = tid >> 5, l = tid & 31;
    const int item = blockIdx.x;

    const float* xs; const float* xn; int S;
    if (item < nA) { xs = xsA + (long)item * 256;  xn = xnA + (long)item * SA * 256;  S = SA; }
    else           { int b = item - nA;
                     xs = xsB + (long)b * 256;     xn = xnB + (long)b * SB * 256;     S = SB; }

    // self logits (warp 0, from global)
    if (w == 0) {
        float sl[4] = {0.f, 0.f, 0.f, 0.f};
        #pragma unroll
        for (int fi = 0; fi < 2; fi++) {
            const int f = l * 4 + fi * 128;
            const float4 xv = *(const float4*)(xs + f);
            #pragma unroll
            for (int h = 0; h < 4; h++) {
                const float4 av = *(const float4*)(a_self + h * 256 + f);
                sl[h] += xv.x * av.x + xv.y * av.y + xv.z * av.z + xv.w * av.w;
            }
        }
        #pragma unroll
        for (int h = 0; h < 4; h++) {
            float v = sl[h];
            #pragma unroll
            for (int o = 16; o; o >>= 1) v += __shfl_down_sync(0xffffffffu, v, o);
            if (l == 0) slself[h] = v;
        }
    }

    // pass 1: neighbor-side logits straight from GLOBAL (rows t = w + 4*ti)
    {
        float4 avn[4][2];
        #pragma unroll
        for (int h = 0; h < 4; h++)
            #pragma unroll
            for (int fi = 0; fi < 2; fi++)
                avn[h][fi] = *(const float4*)(a_neigh + h * 256 + l * 4 + fi * 128);

        {
            float lg[4][4] = {};
            #pragma unroll
            for (int ti = 0; ti < 4; ti++) {
                const int t = w + ti * 4;
                if (t <= S) {
                    const float* row = (t == 0) ? xs : (xn + (long)(t - 1) * 256);
                    #pragma unroll
                    for (int fi = 0; fi < 2; fi++) {
                        const float4 xv = *(const float4*)(row + l * 4 + fi * 128);
                        #pragma unroll
                        for (int h = 0; h < 4; h++)
                            lg[ti][h] += xv.x * avn[h][fi].x + xv.y * avn[h][fi].y
                                       + xv.z * avn[h][fi].z + xv.w * avn[h][fi].w;
                    }
                }
            }
            #pragma unroll
            for (int ti = 0; ti < 4; ti++) {
                const int t = w + ti * 4;
                #pragma unroll
                for (int h = 0; h < 4; h++) {
                    float v = lg[ti][h];
                    #pragma unroll
                    for (int o = 16; o; o >>= 1) v += __shfl_down_sync(0xffffffffu, v, o);
                    if (l == 0 && t <= S) slog[t * 4 + h] = v;
                }
            }
        }
        {
            float lg[3][4] = {};
            #pragma unroll
            for (int ti = 0; ti < 3; ti++) {
                const int t = w + (ti + 4) * 4;
                if (t <= S) {
                    const float* row = (t == 0) ? xs : (xn + (long)(t - 1) * 256);
                    #pragma unroll
                    for (int fi = 0; fi < 2; fi++) {
                        const float4 xv = *(const float4*)(row + l * 4 + fi * 128);
                        #pragma unroll
                        for (int h = 0; h < 4; h++)
                            lg[ti][h] += xv.x * avn[h][fi].x + xv.y * avn[h][fi].y
                                       + xv.z * avn[h][fi].z + xv.w * avn[h][fi].w;
                    }
                }
            }
            #pragma unroll
            for (int ti = 0; ti < 3; ti++) {
                const int t = w + (ti + 4) * 4;
                #pragma unroll
                for (int h = 0; h < 4; h++) {
                    float v = lg[ti][h];
                    #pragma unroll
                    for (int o = 16; o; o >>= 1) v += __shfl_down_sync(0xffffffffu, v, o);
                    if (l == 0 && t <= S) slog[t * 4 + h] = v;
                }
            }
        }
    }
    __syncthreads();

    // leaky-relu + softmax over S+1 (one warp, lane = s)
    if (tid < 32) {
        const bool act = (l <= S);
        float z[4];
        #pragma unroll
        for (int h = 0; h < 4; h++) {
            float v = act ? (slself[h] + slog[l * 4 + h]) : -1e30f;
            z[h] = (v >= 0.f) ? v : NEG_SLOPE * v;
        }
        #pragma unroll
        for (int h = 0; h < 4; h++) {
            float m = z[h];
            #pragma unroll
            for (int o = 16; o; o >>= 1) m = fmaxf(m, __shfl_xor_sync(0xffffffffu, m, o));
            const float ev = act ? __expf(z[h] - m) : 0.f;
            float s = ev;
            #pragma unroll
            for (int o = 16; o; o >>= 1) s += __shfl_xor_sync(0xffffffffu, s, o);
            if (act) slog[l * 4 + h] = ev / s;
        }
    }
    __syncthreads();

    // pass 2: aggregation — thread owns float2 column (tid*2), reads rows from L2
    {
        float2 a0 = make_float2(0.f, 0.f), a1 = make_float2(0.f, 0.f);
        float2 a2 = make_float2(0.f, 0.f), a3 = make_float2(0.f, 0.f);
        const int co = tid * 2;
        {
            // s = 0 (self)
            const float2 xv = *(const float2*)(xs + co);
            const float4 at = *(const float4*)(slog);
            a0.x += at.x * xv.x; a0.y += at.x * xv.y;
            a1.x += at.y * xv.x; a1.y += at.y * xv.y;
            a2.x += at.z * xv.x; a2.y += at.z * xv.y;
            a3.x += at.w * xv.x; a3.y += at.w * xv.y;
        }
        const float* ncol = xn + co;
        #pragma unroll 5
        for (int s = 1; s <= S; s++) {
            const float2 xv = *(const float2*)(ncol + (long)(s - 1) * 256);
            const float4 at = *(const float4*)(slog + s * 4);
            a0.x += at.x * xv.x; a0.y += at.x * xv.y;
            a1.x += at.y * xv.x; a1.y += at.y * xv.y;
            a2.x += at.z * xv.x; a2.y += at.z * xv.y;
            a3.x += at.w * xv.x; a3.y += at.w * xv.y;
        }
        __nv_bfloat16* yoh = yh + (long)item * 1024 + co;
        __nv_bfloat16* yol = yl + (long)item * 1024 + co;
        uint32_t lo;
        uint32_t hi = bfsplit2(a0.x, a0.y, lo);
        *(uint32_t*)(yoh + 0 * 256) = hi; *(uint32_t*)(yol + 0 * 256) = lo;
        hi = bfsplit2(a1.x, a1.y, lo);
        *(uint32_t*)(yoh + 1 * 256) = hi; *(uint32_t*)(yol + 1 * 256) = lo;
        hi = bfsplit2(a2.x, a2.y, lo);
        *(uint32_t*)(yoh + 2 * 256) = hi; *(uint32_t*)(yol + 2 * 256) = lo;
        hi = bfsplit2(a3.x, a3.y, lo);
        *(uint32_t*)(yoh + 3 * 256) = hi; *(uint32_t*)(yol + 3 * 256) = lo;
    }
}

// ---------------- F=512 attention: 128 threads, 8 CTAs/SM (proven) ----------------
__global__ void __launch_bounds__(128, 8)
gat_attn512(const float* __restrict__ xs0, const float* __restrict__ xn0, int S,
            const float* __restrict__ a_self, const float* __restrict__ a_neigh,
            __nv_bfloat16* __restrict__ yh, __nv_bfloat16* __restrict__ yl)
{
    extern __shared__ float sm[];
    float* sx     = sm;                 // 11*512
    float* slog   = sm + 11 * 512;      // 11*4
    float* slself = slog + 11 * 4;      // 4

    const int tid = threadIdx.x;
    const int w = tid >> 5, l = tid & 31;
    const int item = blockIdx.x;

    const float* xs = xs0 + (long)item * 512;
    const float* xn = xn0 + (long)item * S * 512;

    {
        const uint32_t sx_u = smem_u32(sx);
        const float4* s4 = (const float4*)xs;
        for (int i = tid; i < 128; i += 128) CP16(sx_u + i * 16, s4 + i);
        const float4* n4 = (const float4*)xn;
        for (int i = tid; i < S * 128; i += 128) CP16(sx_u + (128 + i) * 16, n4 + i);
        CP_COMMIT();
    }

    if (w == 0) {
        float sl[4] = {0.f, 0.f, 0.f, 0.f};
        #pragma unroll
        for (int c = 0; c < 2; c++) {
            #pragma unroll
            for (int fi = 0; fi < 2; fi++) {
                const int f = c * 256 + l * 4 + fi * 128;
                const float4 xv = *(const float4*)(xs + f);
                #pragma unroll
                for (int h = 0; h < 4; h++) {
                    const float4 av = *(const float4*)(a_self + h * 512 + f);
                    sl[h] += xv.x * av.x + xv.y * av.y + xv.z * av.z + xv.w * av.w;
                }
            }
        }
        #pragma unroll
        for (int h = 0; h < 4; h++) {
            float v = sl[h];
            #pragma unroll
            for (int o = 16; o; o >>= 1) v += __shfl_down_sync(0xffffffffu, v, o);
            if (l == 0) slself[h] = v;
        }
    }
    CP_WAIT0();
    __syncthreads();

    {
        float lg[3][4] = {};
        #pragma unroll
        for (int c = 0; c < 2; c++) {
            float4 avn[4][2];
            #pragma unroll
            for (int h = 0; h < 4; h++)
                #pragma unroll
                for (int fi = 0; fi < 2; fi++)
                    avn[h][fi] = *(const float4*)(a_neigh + h * 512 + c * 256 + l * 4 + fi * 128);
            #pragma unroll
            for (int ti = 0; ti < 3; ti++) {
                const int t = w + ti * 4;
                if (t <= S) {
                    const float* row = sx + t * 512 + c * 256;
                    #pragma unroll
                    for (int fi = 0; fi < 2; fi++) {
                        const float4 xv = *(const float4*)(row + l * 4 + fi * 128);
                        #pragma unroll
                        for (int h = 0; h < 4; h++)
                            lg[ti][h] += xv.x * avn[h][fi].x + xv.y * avn[h][fi].y
                                       + xv.z * avn[h][fi].z + xv.w * avn[h][fi].w;
                    }
                }
            }
        }
        #pragma unroll
        for (int ti = 0; ti < 3; ti++) {
            const int t = w + ti * 4;
            #pragma unroll
            for (int h = 0; h < 4; h++) {
                float v = lg[ti][h];
                #pragma unroll
                for (int o = 16; o; o >>= 1) v += __shfl_down_sync(0xffffffffu, v, o);
                if (l == 0 && t <= S) slog[t * 4 + h] = v;
            }
        }
    }
    __syncthreads();

    if (tid < 32) {
        const bool act = (l <= S);
        float z[4];
        #pragma unroll
        for (int h = 0; h < 4; h++) {
            float v = act ? (slself[h] + slog[l * 4 + h]) : -1e30f;
            z[h] = (v >= 0.f) ? v : NEG_SLOPE * v;
        }
        #pragma unroll
        for (int h = 0; h < 4; h++) {
            float m = z[h];
            #pragma unroll
            for (int o = 16; o; o >>= 1) m = fmaxf(m, __shfl_xor_sync(0xffffffffu, m, o));
            const float ev = act ? __expf(z[h] - m) : 0.f;
            float s = ev;
            #pragma unroll
            for (int o = 16; o; o >>= 1) s += __shfl_xor_sync(0xffffffffu, s, o);
            if (act) slog[l * 4 + h] = ev / s;
        }
    }
    __syncthreads();

    {
        const int fi = tid;               // 0..127 f4-columns
        float4 acc4[4];
        #pragma unroll
        for (int h = 0; h < 4; h++) acc4[h] = make_float4(0.f, 0.f, 0.f, 0.f);
        for (int s = 0; s <= S; s++) {
            const float4 xv = *(const float4*)(sx + s * 512 + fi * 4);
            const float4 at = *(const float4*)(slog + s * 4);
            acc4[0].x += at.x * xv.x; acc4[0].y += at.x * xv.y; acc4[0].z += at.x * xv.z; acc4[0].w += at.x * xv.w;
            acc4[1].x += at.y * xv.x; acc4[1].y += at.y * xv.y; acc4[1].z += at.y * xv.z; acc4[1].w += at.y * xv.w;
            acc4[2].x += at.z * xv.x; acc4[2].y += at.z * xv.y; acc4[2].z += at.z * xv.z; acc4[2].w += at.z * xv.w;
            acc4[3].x += at.w * xv.x; acc4[3].y += at.w * xv.y; acc4[3].z += at.w * xv.z; acc4[3].w += at.w * xv.w;
        }
        __nv_bfloat16* yoh = yh + (long)item * 2048;
        __nv_bfloat16* yol = yl + (long)item * 2048;
        #pragma unroll
        for (int h = 0; h < 4; h++) {
            uint32_t lo01, lo23;
            const uint32_t hi01 = bfsplit2(acc4[h].x, acc4[h].y, lo01);
            const uint32_t hi23 = bfsplit2(acc4[h].z, acc4[h].w, lo23);
            *(uint2*)(yoh + h * 512 + fi * 4) = make_uint2(hi01, hi23);
            *(uint2*)(yol + h * 512 + fi * 4) = make_uint2(lo01, lo23);
        }
    }
}

// ---------------- 8-way partial reduce ----------------
__global__ void reduce8(const float4* __restrict__ p, float4* __restrict__ out, int n4)
{
    const int i = blockIdx.x * blockDim.x + threadIdx.x;
    if (i < n4) {
        float4 s = p[i];
        #pragma unroll
        for (int j = 1; j < 8; j++) {
            const float4 v = p[i + j * n4];
            s.x += v.x; s.y += v.y; s.z += v.z; s.w += v.w;
        }
        out[i] = s;
    }
}

// ---------------- launch ----------------
template <typename T>
static T* sym_addr(const void* symbol)
{
    void* p = nullptr;
    cudaGetSymbolAddress(&p, symbol);
    return (T*)p;
}

extern "C" void kernel_launch(void* const* d_in, const int* in_sizes, int n_in,
                              void* d_out, int out_size)
{
    const float* x0  = (const float*)d_in[0];
    const float* x1  = (const float*)d_in[1];
    const float* x2  = (const float*)d_in[2];
    const float* w0  = (const float*)d_in[3];
    const float* a0s = (const float*)d_in[4];
    const float* a0n = (const float*)d_in[5];
    const float* w1  = (const float*)d_in[6];
    const float* a1s = (const float*)d_in[7];
    const float* a1n = (const float*)d_in[8];
    const float* fcw = (const float*)d_in[9];
    float* out = (float*)d_out;

    const int Bn   = in_sizes[0] / 256;        // 1024
    const int nA   = Bn * 10;                  // 10240
    const int nTot = nA + Bn;                  // 11264

    __nv_bfloat16* yh   = sym_addr<__nv_bfloat16>(g_yh);
    __nv_bfloat16* yl   = sym_addr<__nv_bfloat16>(g_yl);
    float*         hb   = sym_addr<float>(g_h);
    __nv_bfloat16* y2h  = sym_addr<__nv_bfloat16>(g_y2h);
    __nv_bfloat16* y2l  = sym_addr<__nv_bfloat16>(g_y2l);
    float*         W2   = sym_addr<float>(g_W2);
    __nv_bfloat16* Wt2h = sym_addr<__nv_bfloat16>(g_Wt2h);
    __nv_bfloat16* Wt2l = sym_addr<__nv_bfloat16>(g_Wt2l);
    __nv_bfloat16* Wt0h = sym_addr<__nv_bfloat16>(g_Wt0h);
    __nv_bfloat16* Wt0l = sym_addr<__nv_bfloat16>(g_Wt0l);
    float*         part = sym_addr<float>(g_part);

    const int smemB = (2 * 64 + 2 * 128) * LRow * 2;   // 55296 bytes
    cudaFuncSetAttribute(gemm_hmma, cudaFuncAttributeMaxDynamicSharedMemorySize, smemB);
    cudaFuncSetAttribute(gemm_hmma_pre, cudaFuncAttributeMaxDynamicSharedMemorySize, smemB);

    const int smemA1 = (11 * 512 + 11 * 4 + 8) * 4;   // ~22.7 KB
    cudaFuncSetAttribute(gat_attn512, cudaFuncAttributeMaxDynamicSharedMemorySize, smemA1);

    // ---- W2 fold ----
    gemm_hmma<<<dim3(8, 2, NHEAD), 256, smemB>>>(
        w1, fcw, W2, 128,
        128, (long)512 * 128,
        256, (long)128 * 256,
        256, (long)512 * 256);

    // ---- weight transposes + splits ----
    transpose_split<<<dim3(16, 8, NHEAD), dim3(32, 8)>>>(W2, Wt2h, Wt2l, 512, 256);
    transpose_split<<<dim3(8, 4, NHEAD), dim3(32, 8)>>>(w0, Wt0h, Wt0l, 256, 128);

    // ---- layer-0 attention: smem-free 2-pass ----
    gat_attn256<<<nTot, 128>>>(x1, x2, 25, nA,
                               x0, x1, 10,
                               a0s, a0n, yh, yl);

    // ---- layer-0 projection: hb = y @ w0 per head ----
    gemm_hmma_pre<<<dim3(nTot / 64, 1, NHEAD), 256, smemB>>>(
        yh, yl, Wt0h, Wt0l, hb,
        /*kLen*/256, /*kStride*/256, /*nSplit*/1,
        /*lda*/1024, /*aHead*/256, /*wHead*/(long)128 * 256,
        /*ldc*/512, /*cSeg*/128);

    // ---- layer-1 attention: 128 threads, 8 CTAs/SM ----
    gat_attn512<<<Bn, 128, smemA1>>>(hb + (long)nA * 512, hb, 10,
                                     a1s, a1n, y2h, y2l);

    // ---- folded back-end, split-K x2 ----
    gemm_hmma_pre<<<dim3(Bn / 64, 2, NHEAD * 2), 256, smemB>>>(
        y2h, y2l, Wt2h, Wt2l, part,
        /*kLen*/256, /*kStride*/512, /*nSplit*/2,
        /*lda*/2048, /*aHead*/512, /*wHead*/(long)256 * 512,
        /*ldc*/256, /*cSeg*/(long)Bn * 256);

    // ---- out = sum over 8 partials ----
    const int n4 = Bn * 256 / 4;
    reduce8<<<(n4 + 255) / 256, 256>>>((const float4*)part, (float4*)out, n4);
}

// round 16
// speedup vs baseline: 1.0616x; 1.0616x over previous
#include <cuda_runtime.h>
#include <cuda_bf16.h>
#include <cstdint>

#define NHEAD 4
#define NEG_SLOPE 0.2f

// ---------------- scratch (allocation-free: __device__ globals) ----------------
__device__ __nv_bfloat16 g_yh  [11264 * 1024];   // layer-0 aggregates, bf16 hi
__device__ __nv_bfloat16 g_yl  [11264 * 1024];   // layer-0 aggregates, bf16 lo
__device__ float         g_h   [11264 * 512];    // layer-0 outputs (f32)
__device__ __nv_bfloat16 g_y2h [1024 * 2048];    // layer-1 aggregates hi
__device__ __nv_bfloat16 g_y2l [1024 * 2048];    // layer-1 aggregates lo
__device__ __nv_bfloat16 g_Wt2h[NHEAD * 256 * 512];   // folded W2, transposed+split
__device__ __nv_bfloat16 g_Wt2l[NHEAD * 256 * 512];
__device__ __nv_bfloat16 g_Wt0h[NHEAD * 128 * 256];   // w0 transposed+split
__device__ __nv_bfloat16 g_Wt0l[NHEAD * 128 * 256];
__device__ float         g_part[8 * 1024 * 256];      // per-(head,ksplit) partial outputs

// ---------------- helpers ----------------
__device__ __forceinline__ uint32_t smem_u32(const void* p) {
    uint32_t a;
    asm("{ .reg .u64 t; cvta.to.shared.u64 t, %1; cvt.u32.u64 %0, t; }" : "=r"(a) : "l"(p));
    return a;
}
#define CP16(d, s)  asm volatile("cp.async.cg.shared.global [%0], [%1], 16;" :: "r"(d), "l"(s))
#define CP_COMMIT() asm volatile("cp.async.commit_group;" ::: "memory")
#define CP_WAIT0()  asm volatile("cp.async.wait_group 0;" ::: "memory")

__device__ __forceinline__ uint32_t bfsplit2(float v0, float v1, uint32_t& lopk) {
    const unsigned short h0 = __bfloat16_as_ushort(__float2bfloat16_rn(v0));
    const unsigned short h1 = __bfloat16_as_ushort(__float2bfloat16_rn(v1));
    const float r0 = v0 - __bfloat162float(__ushort_as_bfloat16(h0));
    const float r1 = v1 - __bfloat162float(__ushort_as_bfloat16(h1));
    const unsigned short l0 = __bfloat16_as_ushort(__float2bfloat16_rn(r0));
    const unsigned short l1 = __bfloat16_as_ushort(__float2bfloat16_rn(r1));
    lopk = (uint32_t)l0 | ((uint32_t)l1 << 16);
    return (uint32_t)h0 | ((uint32_t)h1 << 16);
}

__device__ __forceinline__ void mma_bf16(float* d, const uint32_t* a, const uint32_t* b) {
    asm volatile(
        "mma.sync.aligned.m16n8k16.row.col.f32.bf16.bf16.f32 "
        "{%0,%1,%2,%3}, {%4,%5,%6,%7}, {%8,%9}, {%0,%1,%2,%3};"
        : "+f"(d[0]), "+f"(d[1]), "+f"(d[2]), "+f"(d[3])
        : "r"(a[0]), "r"(a[1]), "r"(a[2]), "r"(a[3]), "r"(b[0]), "r"(b[1]));
}

#define LRow 72

// ---------------- fold GEMM: W2t[h] = (w1[h] @ fcw[h-slice]) transposed+split ----------------
// Computes C[m][n] = sum_k w1[h][m][k] * fcw[h*128+k][n] (M=512, K=128, N=256),
// then writes Wt2h/Wt2l at [h][n][m] (bf16 hi/lo) directly from accumulators.
__global__ __launch_bounds__(256)
void gemm_hmma_fold(const float* __restrict__ A, const float* __restrict__ W,
                    __nv_bfloat16* __restrict__ Oh, __nv_bfloat16* __restrict__ Ol)
{
    extern __shared__ unsigned short smem[];
    unsigned short* AsH = smem;
    unsigned short* AsL = smem + 64 * LRow;
    unsigned short* BsH = smem + 2 * 64 * LRow;
    unsigned short* BsL = BsH + 128 * LRow;

    const int tid  = threadIdx.x;
    const int wid  = tid >> 5;
    const int lane = tid & 31;
    const int g    = lane >> 2;
    const int t    = lane & 3;
    const int wm   = (wid >> 2) * 32;
    const int wn   = (wid & 3) * 32;

    const int m0 = blockIdx.x * 64;
    const int bn = blockIdx.y * 128;
    const int h  = blockIdx.z;
    const float* Ah = A + (long)h * 512 * 128;          // w1[h], lda=128
    const float* Wh = W + (long)h * 128 * 256;          // fcw slice, ldw=256
    __nv_bfloat16* OhH = Oh + (long)h * 256 * 512;      // [n][m], ld=512
    __nv_bfloat16* OlH = Ol + (long)h * 256 * 512;

    float acc[2][4][4];
    #pragma unroll
    for (int i = 0; i < 2; i++)
        #pragma unroll
        for (int j = 0; j < 4; j++)
            #pragma unroll
            for (int q = 0; q < 4; q++) acc[i][j][q] = 0.f;

    // K = 128 -> 2 chunks of 64
    for (int s = 0; s < 2; s++) {
        const int k0 = s * 64;
        __syncthreads();

        #pragma unroll
        for (int i = 0; i < 4; i++) {
            const int idx = tid + i * 256;
            const int row = idx >> 4;
            const int c4  = (idx & 15) * 4;
            const float4 v = *(const float4*)(Ah + (long)(m0 + row) * 128 + k0 + c4);
            uint32_t lo0, lo1;
            const uint32_t hi0 = bfsplit2(v.x, v.y, lo0);
            const uint32_t hi1 = bfsplit2(v.z, v.w, lo1);
            *(uint2*)&AsH[row * LRow + c4] = make_uint2(hi0, hi1);
            *(uint2*)&AsL[row * LRow + c4] = make_uint2(lo0, lo1);
        }
        {
            const int n  = tid & 127;
            const int kb = (tid >> 7) * 32;
            #pragma unroll
            for (int jq = 0; jq < 4; jq++) {
                uint32_t hi[4], lo[4];
                #pragma unroll
                for (int j2 = 0; j2 < 4; j2++) {
                    const int k = k0 + kb + jq * 8 + j2 * 2;
                    const float v0 = Wh[(long)k * 256 + bn + n];
                    const float v1 = Wh[(long)(k + 1) * 256 + bn + n];
                    hi[j2] = bfsplit2(v0, v1, lo[j2]);
                }
                *(uint4*)&BsH[n * LRow + kb + jq * 8] = make_uint4(hi[0], hi[1], hi[2], hi[3]);
                *(uint4*)&BsL[n * LRow + kb + jq * 8] = make_uint4(lo[0], lo[1], lo[2], lo[3]);
            }
        }
        __syncthreads();

        #pragma unroll
        for (int kk = 0; kk < 64; kk += 16) {
            uint32_t ah[2][4], al[2][4];
            #pragma unroll
            for (int mt = 0; mt < 2; mt++) {
                const int r = wm + mt * 16;
                const int ca = kk + t * 2;
                ah[mt][0] = *(const uint32_t*)&AsH[(r + g)     * LRow + ca];
                ah[mt][1] = *(const uint32_t*)&AsH[(r + 8 + g) * LRow + ca];
                ah[mt][2] = *(const uint32_t*)&AsH[(r + g)     * LRow + ca + 8];
                ah[mt][3] = *(const uint32_t*)&AsH[(r + 8 + g) * LRow + ca + 8];
                al[mt][0] = *(const uint32_t*)&AsL[(r + g)     * LRow + ca];
                al[mt][1] = *(const uint32_t*)&AsL[(r + 8 + g) * LRow + ca];
                al[mt][2] = *(const uint32_t*)&AsL[(r + g)     * LRow + ca + 8];
                al[mt][3] = *(const uint32_t*)&AsL[(r + 8 + g) * LRow + ca + 8];
            }
            uint32_t bh[4][2], bl[4][2];
            #pragma unroll
            for (int nt = 0; nt < 4; nt++) {
                const int n = wn + nt * 8 + g;
                const int cb = kk + t * 2;
                bh[nt][0] = *(const uint32_t*)&BsH[n * LRow + cb];
                bh[nt][1] = *(const uint32_t*)&BsH[n * LRow + cb + 8];
                bl[nt][0] = *(const uint32_t*)&BsL[n * LRow + cb];
                bl[nt][1] = *(const uint32_t*)&BsL[n * LRow + cb + 8];
            }
            #pragma unroll
            for (int mt = 0; mt < 2; mt++)
                #pragma unroll
                for (int nt = 0; nt < 4; nt++) {
                    mma_bf16(acc[mt][nt], ah[mt], bh[nt]);
                    mma_bf16(acc[mt][nt], ah[mt], bl[nt]);
                    mma_bf16(acc[mt][nt], al[mt], bh[nt]);
                }
        }
    }

    // epilogue: transpose+split directly to bf16 [n][m]
    #pragma unroll
    for (int mt = 0; mt < 2; mt++)
        #pragma unroll
        for (int nt = 0; nt < 4; nt++) {
            const int r = m0 + wm + mt * 16 + g;
            const int n = bn + wn + nt * 8 + t * 2;
            #pragma unroll
            for (int q = 0; q < 4; q++) {
                const int rr = r + (q >= 2 ? 8 : 0);
                const int nn = n + (q & 1);
                const float v = acc[mt][nt][q];
                const __nv_bfloat16 hv = __float2bfloat16_rn(v);
                OhH[(long)nn * 512 + rr] = hv;
                OlH[(long)nn * 512 + rr] = __float2bfloat16_rn(v - __bfloat162float(hv));
            }
        }
}

// ---------------- pre-split bf16 HMMA GEMM, register prefetch + split-K (proven) ----------------
__global__ __launch_bounds__(256)
void gemm_hmma_pre(const __nv_bfloat16* __restrict__ Ahg, const __nv_bfloat16* __restrict__ Alg,
                   const __nv_bfloat16* __restrict__ Whg, const __nv_bfloat16* __restrict__ Wlg,
                   float* __restrict__ C,
                   int kLen, int kStride, int nSplit,
                   int lda, long aHeadStride, long wHeadStride,
                   int ldc, long cSegStride)
{
    extern __shared__ unsigned short smem[];
    unsigned short* AsH = smem;
    unsigned short* AsL = smem + 64 * LRow;
    unsigned short* BsH = smem + 2 * 64 * LRow;
    unsigned short* BsL = BsH + 128 * LRow;

    const int tid  = threadIdx.x;
    const int wid  = tid >> 5;
    const int lane = tid & 31;
    const int g    = lane >> 2;
    const int t    = lane & 3;
    const int wm   = (wid >> 2) * 32;
    const int wn   = (wid & 3) * 32;

    const int m0 = blockIdx.x * 64;
    const int bn = blockIdx.y * 128;
    const int z  = blockIdx.z;
    const int h  = z / nSplit;
    const int kOff = (z % nSplit) * kLen;

    const unsigned short* pAh = (const unsigned short*)Ahg + (long)h * aHeadStride + kOff;
    const unsigned short* pAl = (const unsigned short*)Alg + (long)h * aHeadStride + kOff;
    const unsigned short* pWh = (const unsigned short*)Whg + (long)h * wHeadStride + (long)bn * kStride + kOff;
    const unsigned short* pWl = (const unsigned short*)Wlg + (long)h * wHeadStride + (long)bn * kStride + kOff;
    float* Ch = C + (long)z * cSegStride;

    float acc[2][4][4];
    #pragma unroll
    for (int i = 0; i < 2; i++)
        #pragma unroll
        for (int j = 0; j < 4; j++)
            #pragma unroll
            for (int q = 0; q < 4; q++) acc[i][j][q] = 0.f;

    const int arow = tid >> 3, ac8 = (tid & 7) * 8;
    const int brow = tid >> 3, bc8 = (tid & 7) * 8;

    uint4 ra[2], rl[2], rb[4], rbl[4];

    auto ldg = [&](int k0) {
        #pragma unroll
        for (int i = 0; i < 2; i++) {
            const long off = (long)(m0 + arow + i * 32) * lda + k0 + ac8;
            ra[i] = *(const uint4*)(pAh + off);
            rl[i] = *(const uint4*)(pAl + off);
        }
        #pragma unroll
        for (int i = 0; i < 4; i++) {
            const long off = (long)(brow + i * 32) * kStride + k0 + bc8;
            rb[i]  = *(const uint4*)(pWh + off);
            rbl[i] = *(const uint4*)(pWl + off);
        }
    };
    auto sts = [&]() {
        #pragma unroll
        for (int i = 0; i < 2; i++) {
            const int o = (arow + i * 32) * LRow + ac8;
            *(uint2*)&AsH[o]     = make_uint2(ra[i].x, ra[i].y);
            *(uint2*)&AsH[o + 4] = make_uint2(ra[i].z, ra[i].w);
            *(uint2*)&AsL[o]     = make_uint2(rl[i].x, rl[i].y);
            *(uint2*)&AsL[o + 4] = make_uint2(rl[i].z, rl[i].w);
        }
        #pragma unroll
        for (int i = 0; i < 4; i++) {
            const int o = (brow + i * 32) * LRow + bc8;
            *(uint2*)&BsH[o]     = make_uint2(rb[i].x, rb[i].y);
            *(uint2*)&BsH[o + 4] = make_uint2(rb[i].z, rb[i].w);
            *(uint2*)&BsL[o]     = make_uint2(rbl[i].x, rbl[i].y);
            *(uint2*)&BsL[o + 4] = make_uint2(rbl[i].z, rbl[i].w);
        }
    };
    auto compute = [&]() {
        #pragma unroll
        for (int kk = 0; kk < 64; kk += 16) {
            uint32_t ah[2][4], al[2][4];
            #pragma unroll
            for (int mt = 0; mt < 2; mt++) {
                const int r = wm + mt * 16;
                const int ca = kk + t * 2;
                ah[mt][0] = *(const uint32_t*)&AsH[(r + g)     * LRow + ca];
                ah[mt][1] = *(const uint32_t*)&AsH[(r + 8 + g) * LRow + ca];
                ah[mt][2] = *(const uint32_t*)&AsH[(r + g)     * LRow + ca + 8];
                ah[mt][3] = *(const uint32_t*)&AsH[(r + 8 + g) * LRow + ca + 8];
                al[mt][0] = *(const uint32_t*)&AsL[(r + g)     * LRow + ca];
                al[mt][1] = *(const uint32_t*)&AsL[(r + 8 + g) * LRow + ca];
                al[mt][2] = *(const uint32_t*)&AsL[(r + g)     * LRow + ca + 8];
                al[mt][3] = *(const uint32_t*)&AsL[(r + 8 + g) * LRow + ca + 8];
            }
            uint32_t bh[4][2], bl[4][2];
            #pragma unroll
            for (int nt = 0; nt < 4; nt++) {
                const int n = wn + nt * 8 + g;
                const int cb = kk + t * 2;
                bh[nt][0] = *(const uint32_t*)&BsH[n * LRow + cb];
                bh[nt][1] = *(const uint32_t*)&BsH[n * LRow + cb + 8];
                bl[nt][0] = *(const uint32_t*)&BsL[n * LRow + cb];
                bl[nt][1] = *(const uint32_t*)&BsL[n * LRow + cb + 8];
            }
            #pragma unroll
            for (int mt = 0; mt < 2; mt++)
                #pragma unroll
                for (int nt = 0; nt < 4; nt++) {
                    mma_bf16(acc[mt][nt], ah[mt], bh[nt]);
                    mma_bf16(acc[mt][nt], ah[mt], bl[nt]);
                    mma_bf16(acc[mt][nt], al[mt], bh[nt]);
                }
        }
    };

    const int nChunks = kLen >> 6;
    ldg(0);
    sts();
    __syncthreads();
    for (int s = 0; s < nChunks; s++) {
        if (s + 1 < nChunks) ldg((s + 1) * 64);
        compute();
        if (s + 1 < nChunks) {
            __syncthreads();
            sts();
            __syncthreads();
        }
    }

    #pragma unroll
    for (int mt = 0; mt < 2; mt++)
        #pragma unroll
        for (int nt = 0; nt < 4; nt++) {
            const int r  = m0 + wm + mt * 16 + g;
            const int cc = bn + wn + nt * 8 + t * 2;
            *(float2*)(Ch + (long)r * ldc + cc)       = make_float2(acc[mt][nt][0], acc[mt][nt][1]);
            *(float2*)(Ch + (long)(r + 8) * ldc + cc) = make_float2(acc[mt][nt][2], acc[mt][nt][3]);
        }
}

// ---------------- tiled transpose + split (w0 only) ----------------
__global__ void transpose_split(const float* __restrict__ in,
                                __nv_bfloat16* __restrict__ outh,
                                __nv_bfloat16* __restrict__ outl,
                                int K, int N)
{
    __shared__ float tile[32][33];
    const int h  = blockIdx.z;
    const int k0 = blockIdx.x * 32;
    const int n0 = blockIdx.y * 32;
    const int tx = threadIdx.x, ty = threadIdx.y;
    const float* ph = in + (long)h * K * N;

    #pragma unroll
    for (int j = 0; j < 32; j += 8)
        tile[ty + j][tx] = ph[(long)(k0 + ty + j) * N + n0 + tx];
    __syncthreads();

    const long ob = (long)h * N * K;
    #pragma unroll
    for (int j = 0; j < 32; j += 8) {
        const float v = tile[tx][ty + j];
        const __nv_bfloat16 hv = __float2bfloat16_rn(v);
        const long o = ob + (long)(n0 + ty + j) * K + k0 + tx;
        outh[o] = hv;
        outl[o] = __float2bfloat16_rn(v - __bfloat162float(hv));
    }
}

// ---------------- F=256 attention (round-14 proven): smem staging, single-pass agg ----------------
__global__ void __launch_bounds__(128, 8)
gat_attn256(const float* __restrict__ xsA, const float* __restrict__ xnA, int SA, int nA,
            const float* __restrict__ xsB, const float* __restrict__ xnB, int SB,
            const float* __restrict__ a_self, const float* __restrict__ a_neigh,
            __nv_bfloat16* __restrict__ yh, __nv_bfloat16* __restrict__ yl)
{
    extern __shared__ float sm[];
    float* sx     = sm;                 // 26*256
    float* slog   = sm + 26 * 256;      // 26*4
    float* slself = slog + 26 * 4;      // 4

    const int tid = threadIdx.x;
    const int w = tid >> 5, l = tid & 31;
    const int item = blockIdx.x;

    const float* xs; const float* xn; int S;
    if (item < nA) { xs = xsA + (long)item * 256;  xn = xnA + (long)item * SA * 256;  S = SA; }
    else           { int b = item - nA;
                     xs = xsB + (long)b * 256;     xn = xnB + (long)b * SB * 256;     S = SB; }

    {
        const uint32_t sx_u = smem_u32(sx);
        const float4* s4 = (const float4*)xs;
        for (int i = tid; i < 64; i += 128) CP16(sx_u + i * 16, s4 + i);
        const float4* n4 = (const float4*)xn;
        for (int i = tid; i < S * 64; i += 128) CP16(sx_u + (64 + i) * 16, n4 + i);
        CP_COMMIT();
    }

    if (w == 0) {
        float sl[4] = {0.f, 0.f, 0.f, 0.f};
        #pragma unroll
        for (int fi = 0; fi < 2; fi++) {
            const int f = l * 4 + fi * 128;
            const float4 xv = *(const float4*)(xs + f);
            #pragma unroll
            for (int h = 0; h < 4; h++) {
                const float4 av = *(const float4*)(a_self + h * 256 + f);
                sl[h] += xv.x * av.x + xv.y * av.y + xv.z * av.z + xv.w * av.w;
            }
        }
        #pragma unroll
        for (int h = 0; h < 4; h++) {
            float v = sl[h];
            #pragma unroll
            for (int o = 16; o; o >>= 1) v += __shfl_down_sync(0xffffffffu, v, o);
            if (l == 0) slself[h] = v;
        }
    }
    CP_WAIT0();
    __syncthreads();

    {
        float4 avn[4][2];
        #pragma unroll
        for (int h = 0; h < 4; h++)
            #pragma unroll
            for (int fi = 0; fi < 2; fi++)
                avn[h][fi] = *(const float4*)(a_neigh + h * 256 + l * 4 + fi * 128);

        {
            float lg[4][4] = {};
            #pragma unroll
            for (int ti = 0; ti < 4; ti++) {
                const int t = w + ti * 4;
                if (t <= S) {
                    const float* row = sx + t * 256;
                    #pragma unroll
                    for (int fi = 0; fi < 2; fi++) {
                        const float4 xv = *(const float4*)(row + l * 4 + fi * 128);
                        #pragma unroll
                        for (int h = 0; h < 4; h++)
                            lg[ti][h] += xv.x * avn[h][fi].x + xv.y * avn[h][fi].y
                                       + xv.z * avn[h][fi].z + xv.w * avn[h][fi].w;
                    }
                }
            }
            #pragma unroll
            for (int ti = 0; ti < 4; ti++) {
                const int t = w + ti * 4;
                #pragma unroll
                for (int h = 0; h < 4; h++) {
                    float v = lg[ti][h];
                    #pragma unroll
                    for (int o = 16; o; o >>= 1) v += __shfl_down_sync(0xffffffffu, v, o);
                    if (l == 0 && t <= S) slog[t * 4 + h] = v;
                }
            }
        }
        {
            float lg[3][4] = {};
            #pragma unroll
            for (int ti = 0; ti < 3; ti++) {
                const int t = w + (ti + 4) * 4;
                if (t <= S) {
                    const float* row = sx + t * 256;
                    #pragma unroll
                    for (int fi = 0; fi < 2; fi++) {
                        const float4 xv = *(const float4*)(row + l * 4 + fi * 128);
                        #pragma unroll
                        for (int h = 0; h < 4; h++)
                            lg[ti][h] += xv.x * avn[h][fi].x + xv.y * avn[h][fi].y
                                       + xv.z * avn[h][fi].z + xv.w * avn[h][fi].w;
                    }
                }
            }
            #pragma unroll
            for (int ti = 0; ti < 3; ti++) {
                const int t = w + (ti + 4) * 4;
                #pragma unroll
                for (int h = 0; h < 4; h++) {
                    float v = lg[ti][h];
                    #pragma unroll
                    for (int o = 16; o; o >>= 1) v += __shfl_down_sync(0xffffffffu, v, o);
                    if (l == 0 && t <= S) slog[t * 4 + h] = v;
                }
            }
        }
    }
    __syncthreads();

    if (tid < 32) {
        const bool act = (l <= S);
        float z[4];
        #pragma unroll
        for (int h = 0; h < 4; h++) {
            float v = act ? (slself[h] + slog[l * 4 + h]) : -1e30f;
            z[h] = (v >= 0.f) ? v : NEG_SLOPE * v;
        }
        #pragma unroll
        for (int h = 0; h < 4; h++) {
            float m = z[h];
            #pragma unroll
            for (int o = 16; o; o >>= 1) m = fmaxf(m, __shfl_xor_sync(0xffffffffu, m, o));
            const float ev = act ? __expf(z[h] - m) : 0.f;
            float s = ev;
            #pragma unroll
            for (int o = 16; o; o >>= 1) s += __shfl_xor_sync(0xffffffffu, s, o);
            if (act) slog[l * 4 + h] = ev / s;
        }
    }
    __syncthreads();

    // aggregation: thread owns float2 column (tid*2), ALL 4 heads — tile read once
    {
        float2 a0 = make_float2(0.f, 0.f), a1 = make_float2(0.f, 0.f);
        float2 a2 = make_float2(0.f, 0.f), a3 = make_float2(0.f, 0.f);
        const float* col = sx + tid * 2;
        for (int s = 0; s <= S; s++) {
            const float2 xv = *(const float2*)(col + s * 256);
            const float4 at = *(const float4*)(slog + s * 4);
            a0.x += at.x * xv.x; a0.y += at.x * xv.y;
            a1.x += at.y * xv.x; a1.y += at.y * xv.y;
            a2.x += at.z * xv.x; a2.y += at.z * xv.y;
            a3.x += at.w * xv.x; a3.y += at.w * xv.y;
        }
        __nv_bfloat16* yoh = yh + (long)item * 1024 + tid * 2;
        __nv_bfloat16* yol = yl + (long)item * 1024 + tid * 2;
        uint32_t lo;
        uint32_t hi = bfsplit2(a0.x, a0.y, lo);
        *(uint32_t*)(yoh + 0 * 256) = hi; *(uint32_t*)(yol + 0 * 256) = lo;
        hi = bfsplit2(a1.x, a1.y, lo);
        *(uint32_t*)(yoh + 1 * 256) = hi; *(uint32_t*)(yol + 1 * 256) = lo;
        hi = bfsplit2(a2.x, a2.y, lo);
        *(uint32_t*)(yoh + 2 * 256) = hi; *(uint32_t*)(yol + 2 * 256) = lo;
        hi = bfsplit2(a3.x, a3.y, lo);
        *(uint32_t*)(yoh + 3 * 256) = hi; *(uint32_t*)(yol + 3 * 256) = lo;
    }
}

// ---------------- F=512 attention: 128 threads, 8 CTAs/SM (proven) ----------------
__global__ void __launch_bounds__(128, 8)
gat_attn512(const float* __restrict__ xs0, const float* __restrict__ xn0, int S,
            const float* __restrict__ a_self, const float* __restrict__ a_neigh,
            __nv_bfloat16* __restrict__ yh, __nv_bfloat16* __restrict__ yl)
{
    extern __shared__ float sm[];
    float* sx     = sm;                 // 11*512
    float* slog   = sm + 11 * 512;      // 11*4
    float* slself = slog + 11 * 4;      // 4

    const int tid = threadIdx.x;
    const int w = tid >> 5, l = tid & 31;
    const int item = blockIdx.x;

    const float* xs = xs0 + (long)item * 512;
    const float* xn = xn0 + (long)item * S * 512;

    {
        const uint32_t sx_u = smem_u32(sx);
        const float4* s4 = (const float4*)xs;
        for (int i = tid; i < 128; i += 128) CP16(sx_u + i * 16, s4 + i);
        const float4* n4 = (const float4*)xn;
        for (int i = tid; i < S * 128; i += 128) CP16(sx_u + (128 + i) * 16, n4 + i);
        CP_COMMIT();
    }

    if (w == 0) {
        float sl[4] = {0.f, 0.f, 0.f, 0.f};
        #pragma unroll
        for (int c = 0; c < 2; c++) {
            #pragma unroll
            for (int fi = 0; fi < 2; fi++) {
                const int f = c * 256 + l * 4 + fi * 128;
                const float4 xv = *(const float4*)(xs + f);
                #pragma unroll
                for (int h = 0; h < 4; h++) {
                    const float4 av = *(const float4*)(a_self + h * 512 + f);
                    sl[h] += xv.x * av.x + xv.y * av.y + xv.z * av.z + xv.w * av.w;
                }
            }
        }
        #pragma unroll
        for (int h = 0; h < 4; h++) {
            float v = sl[h];
            #pragma unroll
            for (int o = 16; o; o >>= 1) v += __shfl_down_sync(0xffffffffu, v, o);
            if (l == 0) slself[h] = v;
        }
    }
    CP_WAIT0();
    __syncthreads();

    {
        float lg[3][4] = {};
        #pragma unroll
        for (int c = 0; c < 2; c++) {
            float4 avn[4][2];
            #pragma unroll
            for (int h = 0; h < 4; h++)
                #pragma unroll
                for (int fi = 0; fi < 2; fi++)
                    avn[h][fi] = *(const float4*)(a_neigh + h * 512 + c * 256 + l * 4 + fi * 128);
            #pragma unroll
            for (int ti = 0; ti < 3; ti++) {
                const int t = w + ti * 4;
                if (t <= S) {
                    const float* row = sx + t * 512 + c * 256;
                    #pragma unroll
                    for (int fi = 0; fi < 2; fi++) {
                        const float4 xv = *(const float4*)(row + l * 4 + fi * 128);
                        #pragma unroll
                        for (int h = 0; h < 4; h++)
                            lg[ti][h] += xv.x * avn[h][fi].x + xv.y * avn[h][fi].y
                                       + xv.z * avn[h][fi].z + xv.w * avn[h][fi].w;
                    }
                }
            }
        }
        #pragma unroll
        for (int ti = 0; ti < 3; ti++) {
            const int t = w + ti * 4;
            #pragma unroll
            for (int h = 0; h < 4; h++) {
                float v = lg[ti][h];
                #pragma unroll
                for (int o = 16; o; o >>= 1) v += __shfl_down_sync(0xffffffffu, v, o);
                if (l == 0 && t <= S) slog[t * 4 + h] = v;
            }
        }
    }
    __syncthreads();

    if (tid < 32) {
        const bool act = (l <= S);
        float z[4];
        #pragma unroll
        for (int h = 0; h < 4; h++) {
            float v = act ? (slself[h] + slog[l * 4 + h]) : -1e30f;
            z[h] = (v >= 0.f) ? v : NEG_SLOPE * v;
        }
        #pragma unroll
        for (int h = 0; h < 4; h++) {
            float m = z[h];
            #pragma unroll
            for (int o = 16; o; o >>= 1) m = fmaxf(m, __shfl_xor_sync(0xffffffffu, m, o));
            const float ev = act ? __expf(z[h] - m) : 0.f;
            float s = ev;
            #pragma unroll
            for (int o = 16; o; o >>= 1) s += __shfl_xor_sync(0xffffffffu, s, o);
            if (act) slog[l * 4 + h] = ev / s;
        }
    }
    __syncthreads();

    {
        const int fi = tid;               // 0..127 f4-columns
        float4 acc4[4];
        #pragma unroll
        for (int h = 0; h < 4; h++) acc4[h] = make_float4(0.f, 0.f, 0.f, 0.f);
        for (int s = 0; s <= S; s++) {
            const float4 xv = *(const float4*)(sx + s * 512 + fi * 4);
            const float4 at = *(const float4*)(slog + s * 4);
            acc4[0].x += at.x * xv.x; acc4[0].y += at.x * xv.y; acc4[0].z += at.x * xv.z; acc4[0].w += at.x * xv.w;
            acc4[1].x += at.y * xv.x; acc4[1].y += at.y * xv.y; acc4[1].z += at.y * xv.z; acc4[1].w += at.y * xv.w;
            acc4[2].x += at.z * xv.x; acc4[2].y += at.z * xv.y; acc4[2].z += at.z * xv.z; acc4[2].w += at.z * xv.w;
            acc4[3].x += at.w * xv.x; acc4[3].y += at.w * xv.y; acc4[3].z += at.w * xv.z; acc4[3].w += at.w * xv.w;
        }
        __nv_bfloat16* yoh = yh + (long)item * 2048;
        __nv_bfloat16* yol = yl + (long)item * 2048;
        #pragma unroll
        for (int h = 0; h < 4; h++) {
            uint32_t lo01, lo23;
            const uint32_t hi01 = bfsplit2(acc4[h].x, acc4[h].y, lo01);
            const uint32_t hi23 = bfsplit2(acc4[h].z, acc4[h].w, lo23);
            *(uint2*)(yoh + h * 512 + fi * 4) = make_uint2(hi01, hi23);
            *(uint2*)(yol + h * 512 + fi * 4) = make_uint2(lo01, lo23);
        }
    }
}

// ---------------- 8-way partial reduce ----------------
__global__ void reduce8(const float4* __restrict__ p, float4* __restrict__ out, int n4)
{
    const int i = blockIdx.x * blockDim.x + threadIdx.x;
    if (i < n4) {
        float4 s = p[i];
        #pragma unroll
        for (int j = 1; j < 8; j++) {
            const float4 v = p[i + j * n4];
            s.x += v.x; s.y += v.y; s.z += v.z; s.w += v.w;
        }
        out[i] = s;
    }
}

// ---------------- launch ----------------
template <typename T>
static T* sym_addr(const void* symbol)
{
    void* p = nullptr;
    cudaGetSymbolAddress(&p, symbol);
    return (T*)p;
}

extern "C" void kernel_launch(void* const* d_in, const int* in_sizes, int n_in,
                              void* d_out, int out_size)
{
    const float* x0  = (const float*)d_in[0];
    const float* x1  = (const float*)d_in[1];
    const float* x2  = (const float*)d_in[2];
    const float* w0  = (const float*)d_in[3];
    const float* a0s = (const float*)d_in[4];
    const float* a0n = (const float*)d_in[5];
    const float* w1  = (const float*)d_in[6];
    const float* a1s = (const float*)d_in[7];
    const float* a1n = (const float*)d_in[8];
    const float* fcw = (const float*)d_in[9];
    float* out = (float*)d_out;

    const int Bn   = in_sizes[0] / 256;        // 1024
    const int nA   = Bn * 10;                  // 10240
    const int nTot = nA + Bn;                  // 11264

    __nv_bfloat16* yh   = sym_addr<__nv_bfloat16>(g_yh);
    __nv_bfloat16* yl   = sym_addr<__nv_bfloat16>(g_yl);
    float*         hb   = sym_addr<float>(g_h);
    __nv_bfloat16* y2h  = sym_addr<__nv_bfloat16>(g_y2h);
    __nv_bfloat16* y2l  = sym_addr<__nv_bfloat16>(g_y2l);
    __nv_bfloat16* Wt2h = sym_addr<__nv_bfloat16>(g_Wt2h);
    __nv_bfloat16* Wt2l = sym_addr<__nv_bfloat16>(g_Wt2l);
    __nv_bfloat16* Wt0h = sym_addr<__nv_bfloat16>(g_Wt0h);
    __nv_bfloat16* Wt0l = sym_addr<__nv_bfloat16>(g_Wt0l);
    float*         part = sym_addr<float>(g_part);

    const int smemB = (2 * 64 + 2 * 128) * LRow * 2;   // 55296 bytes
    cudaFuncSetAttribute(gemm_hmma_fold, cudaFuncAttributeMaxDynamicSharedMemorySize, smemB);
    cudaFuncSetAttribute(gemm_hmma_pre, cudaFuncAttributeMaxDynamicSharedMemorySize, smemB);

    const int smemA0 = (26 * 256 + 26 * 4 + 8) * 4;   // ~27.1 KB
    const int smemA1 = (11 * 512 + 11 * 4 + 8) * 4;   // ~22.7 KB
    cudaFuncSetAttribute(gat_attn256, cudaFuncAttributeMaxDynamicSharedMemorySize, smemA0);
    cudaFuncSetAttribute(gat_attn512, cudaFuncAttributeMaxDynamicSharedMemorySize, smemA1);

    // ---- fold: Wt2[h] = (w1[h] @ fcw[h-slice]) transposed+split, one kernel ----
    gemm_hmma_fold<<<dim3(8, 2, NHEAD), 256, smemB>>>(w1, fcw, Wt2h, Wt2l);

    // ---- w0 transpose+split ----
    transpose_split<<<dim3(8, 4, NHEAD), dim3(32, 8)>>>(w0, Wt0h, Wt0l, 256, 128);

    // ---- layer-0 attention: 128 threads, 8 CTAs/SM ----
    gat_attn256<<<nTot, 128, smemA0>>>(x1, x2, 25, nA,
                                       x0, x1, 10,
                                       a0s, a0n, yh, yl);

    // ---- layer-0 projection: hb = y @ w0 per head ----
    gemm_hmma_pre<<<dim3(nTot / 64, 1, NHEAD), 256, smemB>>>(
        yh, yl, Wt0h, Wt0l, hb,
        /*kLen*/256, /*kStride*/256, /*nSplit*/1,
        /*lda*/1024, /*aHead*/256, /*wHead*/(long)128 * 256,
        /*ldc*/512, /*cSeg*/128);

    // ---- layer-1 attention: 128 threads, 8 CTAs/SM ----
    gat_attn512<<<Bn, 128, smemA1>>>(hb + (long)nA * 512, hb, 10,
                                     a1s, a1n, y2h, y2l);

    // ---- folded back-end, split-K x2 ----
    gemm_hmma_pre<<<dim3(Bn / 64, 2, NHEAD * 2), 256, smemB>>>(
        y2h, y2l, Wt2h, Wt2l, part,
        /*kLen*/256, /*kStride*/512, /*nSplit*/2,
        /*lda*/2048, /*aHead*/512, /*wHead*/(long)256 * 512,
        /*ldc*/256, /*cSeg*/(long)Bn * 256);

    // ---- out = sum over 8 partials ----
    const int n4 = Bn * 256 / 4;
    reduce8<<<(n4 + 255) / 256, 256>>>((const float4*)part, (float4*)out, n4);
}

// round 17
// speedup vs baseline: 1.1180x; 1.0531x over previous
#include <cuda_runtime.h>
#include <cuda_bf16.h>
#include <cstdint>

#define NHEAD 4
#define NEG_SLOPE 0.2f

// ---------------- scratch (allocation-free: __device__ globals) ----------------
__device__ __nv_bfloat16 g_yh  [11264 * 1024];   // layer-0 aggregates, bf16 hi
__device__ __nv_bfloat16 g_yl  [11264 * 1024];   // layer-0 aggregates, bf16 lo
__device__ float         g_h   [11264 * 512];    // layer-0 outputs (f32)
__device__ __nv_bfloat16 g_y2h [1024 * 2048];    // layer-1 aggregates hi
__device__ __nv_bfloat16 g_y2l [1024 * 2048];    // layer-1 aggregates lo
__device__ __nv_bfloat16 g_Wt2h[NHEAD * 256 * 512];   // folded W2, transposed+split
__device__ __nv_bfloat16 g_Wt2l[NHEAD * 256 * 512];
__device__ __nv_bfloat16 g_Wt0h[NHEAD * 128 * 256];   // w0 transposed+split
__device__ __nv_bfloat16 g_Wt0l[NHEAD * 128 * 256];
__device__ float         g_part[8 * 1024 * 256];      // per-(head,ksplit) partial outputs

// ---------------- helpers ----------------
__device__ __forceinline__ uint32_t smem_u32(const void* p) {
    uint32_t a;
    asm("{ .reg .u64 t; cvta.to.shared.u64 t, %1; cvt.u32.u64 %0, t; }" : "=r"(a) : "l"(p));
    return a;
}
#define CP16(d, s)  asm volatile("cp.async.cg.shared.global [%0], [%1], 16;" :: "r"(d), "l"(s))
#define CP_COMMIT() asm volatile("cp.async.commit_group;" ::: "memory")
#define CP_WAIT0()  asm volatile("cp.async.wait_group 0;" ::: "memory")
#define CP_WAIT1()  asm volatile("cp.async.wait_group 1;" ::: "memory")

__device__ __forceinline__ uint32_t bfsplit2(float v0, float v1, uint32_t& lopk) {
    const unsigned short h0 = __bfloat16_as_ushort(__float2bfloat16_rn(v0));
    const unsigned short h1 = __bfloat16_as_ushort(__float2bfloat16_rn(v1));
    const float r0 = v0 - __bfloat162float(__ushort_as_bfloat16(h0));
    const float r1 = v1 - __bfloat162float(__ushort_as_bfloat16(h1));
    const unsigned short l0 = __bfloat16_as_ushort(__float2bfloat16_rn(r0));
    const unsigned short l1 = __bfloat16_as_ushort(__float2bfloat16_rn(r1));
    lopk = (uint32_t)l0 | ((uint32_t)l1 << 16);
    return (uint32_t)h0 | ((uint32_t)h1 << 16);
}

__device__ __forceinline__ void mma_bf16(float* d, const uint32_t* a, const uint32_t* b) {
    asm volatile(
        "mma.sync.aligned.m16n8k16.row.col.f32.bf16.bf16.f32 "
        "{%0,%1,%2,%3}, {%4,%5,%6,%7}, {%8,%9}, {%0,%1,%2,%3};"
        : "+f"(d[0]), "+f"(d[1]), "+f"(d[2]), "+f"(d[3])
        : "r"(a[0]), "r"(a[1]), "r"(a[2]), "r"(a[3]), "r"(b[0]), "r"(b[1]));
}

#define LRow 72
#define STAGE_SHORTS (384 * LRow)   // (2*64 + 2*128) rows * LRow shorts = 27648

// ---------------- fold GEMM: W2t[h] = (w1[h] @ fcw[h-slice]) transposed+split (proven) ----------------
__global__ __launch_bounds__(256)
void gemm_hmma_fold(const float* __restrict__ A, const float* __restrict__ W,
                    __nv_bfloat16* __restrict__ Oh, __nv_bfloat16* __restrict__ Ol)
{
    extern __shared__ unsigned short smem[];
    unsigned short* AsH = smem;
    unsigned short* AsL = smem + 64 * LRow;
    unsigned short* BsH = smem + 2 * 64 * LRow;
    unsigned short* BsL = BsH + 128 * LRow;

    const int tid  = threadIdx.x;
    const int wid  = tid >> 5;
    const int lane = tid & 31;
    const int g    = lane >> 2;
    const int t    = lane & 3;
    const int wm   = (wid >> 2) * 32;
    const int wn   = (wid & 3) * 32;

    const int m0 = blockIdx.x * 64;
    const int bn = blockIdx.y * 128;
    const int h  = blockIdx.z;
    const float* Ah = A + (long)h * 512 * 128;
    const float* Wh = W + (long)h * 128 * 256;
    __nv_bfloat16* OhH = Oh + (long)h * 256 * 512;
    __nv_bfloat16* OlH = Ol + (long)h * 256 * 512;

    float acc[2][4][4];
    #pragma unroll
    for (int i = 0; i < 2; i++)
        #pragma unroll
        for (int j = 0; j < 4; j++)
            #pragma unroll
            for (int q = 0; q < 4; q++) acc[i][j][q] = 0.f;

    for (int s = 0; s < 2; s++) {
        const int k0 = s * 64;
        __syncthreads();

        #pragma unroll
        for (int i = 0; i < 4; i++) {
            const int idx = tid + i * 256;
            const int row = idx >> 4;
            const int c4  = (idx & 15) * 4;
            const float4 v = *(const float4*)(Ah + (long)(m0 + row) * 128 + k0 + c4);
            uint32_t lo0, lo1;
            const uint32_t hi0 = bfsplit2(v.x, v.y, lo0);
            const uint32_t hi1 = bfsplit2(v.z, v.w, lo1);
            *(uint2*)&AsH[row * LRow + c4] = make_uint2(hi0, hi1);
            *(uint2*)&AsL[row * LRow + c4] = make_uint2(lo0, lo1);
        }
        {
            const int n  = tid & 127;
            const int kb = (tid >> 7) * 32;
            #pragma unroll
            for (int jq = 0; jq < 4; jq++) {
                uint32_t hi[4], lo[4];
                #pragma unroll
                for (int j2 = 0; j2 < 4; j2++) {
                    const int k = k0 + kb + jq * 8 + j2 * 2;
                    const float v0 = Wh[(long)k * 256 + bn + n];
                    const float v1 = Wh[(long)(k + 1) * 256 + bn + n];
                    hi[j2] = bfsplit2(v0, v1, lo[j2]);
                }
                *(uint4*)&BsH[n * LRow + kb + jq * 8] = make_uint4(hi[0], hi[1], hi[2], hi[3]);
                *(uint4*)&BsL[n * LRow + kb + jq * 8] = make_uint4(lo[0], lo[1], lo[2], lo[3]);
            }
        }
        __syncthreads();

        #pragma unroll
        for (int kk = 0; kk < 64; kk += 16) {
            uint32_t ah[2][4], al[2][4];
            #pragma unroll
            for (int mt = 0; mt < 2; mt++) {
                const int r = wm + mt * 16;
                const int ca = kk + t * 2;
                ah[mt][0] = *(const uint32_t*)&AsH[(r + g)     * LRow + ca];
                ah[mt][1] = *(const uint32_t*)&AsH[(r + 8 + g) * LRow + ca];
                ah[mt][2] = *(const uint32_t*)&AsH[(r + g)     * LRow + ca + 8];
                ah[mt][3] = *(const uint32_t*)&AsH[(r + 8 + g) * LRow + ca + 8];
                al[mt][0] = *(const uint32_t*)&AsL[(r + g)     * LRow + ca];
                al[mt][1] = *(const uint32_t*)&AsL[(r + 8 + g) * LRow + ca];
                al[mt][2] = *(const uint32_t*)&AsL[(r + g)     * LRow + ca + 8];
                al[mt][3] = *(const uint32_t*)&AsL[(r + 8 + g) * LRow + ca + 8];
            }
            uint32_t bh[4][2], bl[4][2];
            #pragma unroll
            for (int nt = 0; nt < 4; nt++) {
                const int n = wn + nt * 8 + g;
                const int cb = kk + t * 2;
                bh[nt][0] = *(const uint32_t*)&BsH[n * LRow + cb];
                bh[nt][1] = *(const uint32_t*)&BsH[n * LRow + cb + 8];
                bl[nt][0] = *(const uint32_t*)&BsL[n * LRow + cb];
                bl[nt][1] = *(const uint32_t*)&BsL[n * LRow + cb + 8];
            }
            #pragma unroll
            for (int mt = 0; mt < 2; mt++)
                #pragma unroll
                for (int nt = 0; nt < 4; nt++) {
                    mma_bf16(acc[mt][nt], ah[mt], bh[nt]);
                    mma_bf16(acc[mt][nt], ah[mt], bl[nt]);
                    mma_bf16(acc[mt][nt], al[mt], bh[nt]);
                }
        }
    }

    #pragma unroll
    for (int mt = 0; mt < 2; mt++)
        #pragma unroll
        for (int nt = 0; nt < 4; nt++) {
            const int r = m0 + wm + mt * 16 + g;
            const int n = bn + wn + nt * 8 + t * 2;
            #pragma unroll
            for (int q = 0; q < 4; q++) {
                const int rr = r + (q >= 2 ? 8 : 0);
                const int nn = n + (q & 1);
                const float v = acc[mt][nt][q];
                const __nv_bfloat16 hv = __float2bfloat16_rn(v);
                OhH[(long)nn * 512 + rr] = hv;
                OlH[(long)nn * 512 + rr] = __float2bfloat16_rn(v - __bfloat162float(hv));
            }
        }
}

// ---------------- pre-split bf16 HMMA GEMM: cp.async double-buffered, split-K ----------------
__global__ __launch_bounds__(256)
void gemm_hmma_pre(const __nv_bfloat16* __restrict__ Ahg, const __nv_bfloat16* __restrict__ Alg,
                   const __nv_bfloat16* __restrict__ Whg, const __nv_bfloat16* __restrict__ Wlg,
                   float* __restrict__ C,
                   int kLen, int kStride, int nSplit,
                   int lda, long aHeadStride, long wHeadStride,
                   int ldc, long cSegStride)
{
    extern __shared__ unsigned short smem[];   // 2 stages x STAGE_SHORTS

    const int tid  = threadIdx.x;
    const int wid  = tid >> 5;
    const int lane = tid & 31;
    const int g    = lane >> 2;
    const int t    = lane & 3;
    const int wm   = (wid >> 2) * 32;
    const int wn   = (wid & 3) * 32;

    const int m0 = blockIdx.x * 64;
    const int bn = blockIdx.y * 128;
    const int z  = blockIdx.z;
    const int h  = z / nSplit;
    const int kOff = (z % nSplit) * kLen;

    const unsigned short* pAh = (const unsigned short*)Ahg + (long)h * aHeadStride + kOff;
    const unsigned short* pAl = (const unsigned short*)Alg + (long)h * aHeadStride + kOff;
    const unsigned short* pWh = (const unsigned short*)Whg + (long)h * wHeadStride + (long)bn * kStride + kOff;
    const unsigned short* pWl = (const unsigned short*)Wlg + (long)h * wHeadStride + (long)bn * kStride + kOff;
    float* Ch = C + (long)z * cSegStride;

    float acc[2][4][4];
    #pragma unroll
    for (int i = 0; i < 2; i++)
        #pragma unroll
        for (int j = 0; j < 4; j++)
            #pragma unroll
            for (int q = 0; q < 4; q++) acc[i][j][q] = 0.f;

    const int arow = tid >> 3, ac8 = (tid & 7) * 8;   // 32 rows/pass, 8 shorts (16B) per thread

    auto issue = [&](int k0, int stg) {
        unsigned short* base = smem + stg * STAGE_SHORTS;
        unsigned short* AsH = base;
        unsigned short* AsL = base + 64 * LRow;
        unsigned short* BsH = base + 2 * 64 * LRow;
        unsigned short* BsL = BsH + 128 * LRow;
        #pragma unroll
        for (int i = 0; i < 2; i++) {
            const long off = (long)(m0 + arow + i * 32) * lda + k0 + ac8;
            const int o = (arow + i * 32) * LRow + ac8;
            CP16(smem_u32(&AsH[o]), pAh + off);
            CP16(smem_u32(&AsL[o]), pAl + off);
        }
        #pragma unroll
        for (int i = 0; i < 4; i++) {
            const long off = (long)(arow + i * 32) * kStride + k0 + ac8;
            const int o = (arow + i * 32) * LRow + ac8;
            CP16(smem_u32(&BsH[o]), pWh + off);
            CP16(smem_u32(&BsL[o]), pWl + off);
        }
    };

    auto compute = [&](int stg) {
        unsigned short* base = smem + stg * STAGE_SHORTS;
        unsigned short* AsH = base;
        unsigned short* AsL = base + 64 * LRow;
        unsigned short* BsH = base + 2 * 64 * LRow;
        unsigned short* BsL = BsH + 128 * LRow;
        #pragma unroll
        for (int kk = 0; kk < 64; kk += 16) {
            uint32_t ah[2][4], al[2][4];
            #pragma unroll
            for (int mt = 0; mt < 2; mt++) {
                const int r = wm + mt * 16;
                const int ca = kk + t * 2;
                ah[mt][0] = *(const uint32_t*)&AsH[(r + g)     * LRow + ca];
                ah[mt][1] = *(const uint32_t*)&AsH[(r + 8 + g) * LRow + ca];
                ah[mt][2] = *(const uint32_t*)&AsH[(r + g)     * LRow + ca + 8];
                ah[mt][3] = *(const uint32_t*)&AsH[(r + 8 + g) * LRow + ca + 8];
                al[mt][0] = *(const uint32_t*)&AsL[(r + g)     * LRow + ca];
                al[mt][1] = *(const uint32_t*)&AsL[(r + 8 + g) * LRow + ca];
                al[mt][2] = *(const uint32_t*)&AsL[(r + g)     * LRow + ca + 8];
                al[mt][3] = *(const uint32_t*)&AsL[(r + 8 + g) * LRow + ca + 8];
            }
            uint32_t bh[4][2], bl[4][2];
            #pragma unroll
            for (int nt = 0; nt < 4; nt++) {
                const int n = wn + nt * 8 + g;
                const int cb = kk + t * 2;
                bh[nt][0] = *(const uint32_t*)&BsH[n * LRow + cb];
                bh[nt][1] = *(const uint32_t*)&BsH[n * LRow + cb + 8];
                bl[nt][0] = *(const uint32_t*)&BsL[n * LRow + cb];
                bl[nt][1] = *(const uint32_t*)&BsL[n * LRow + cb + 8];
            }
            #pragma unroll
            for (int mt = 0; mt < 2; mt++)
                #pragma unroll
                for (int nt = 0; nt < 4; nt++) {
                    mma_bf16(acc[mt][nt], ah[mt], bh[nt]);
                    mma_bf16(acc[mt][nt], ah[mt], bl[nt]);
                    mma_bf16(acc[mt][nt], al[mt], bh[nt]);
                }
        }
    };

    const int nChunks = kLen >> 6;
    issue(0, 0);
    CP_COMMIT();
    int buf = 0;
    for (int s = 0; s < nChunks; s++) {
        if (s + 1 < nChunks) {
            issue((s + 1) * 64, buf ^ 1);   // async prefetch overlaps compute
            CP_COMMIT();
            CP_WAIT1();                      // chunk s has landed
        } else {
            CP_WAIT0();
        }
        __syncthreads();
        compute(buf);
        __syncthreads();                     // buf free for the prefetch after next
        buf ^= 1;
    }

    #pragma unroll
    for (int mt = 0; mt < 2; mt++)
        #pragma unroll
        for (int nt = 0; nt < 4; nt++) {
            const int r  = m0 + wm + mt * 16 + g;
            const int cc = bn + wn + nt * 8 + t * 2;
            *(float2*)(Ch + (long)r * ldc + cc)       = make_float2(acc[mt][nt][0], acc[mt][nt][1]);
            *(float2*)(Ch + (long)(r + 8) * ldc + cc) = make_float2(acc[mt][nt][2], acc[mt][nt][3]);
        }
}

// ---------------- tiled transpose + split (w0 only) ----------------
__global__ void transpose_split(const float* __restrict__ in,
                                __nv_bfloat16* __restrict__ outh,
                                __nv_bfloat16* __restrict__ outl,
                                int K, int N)
{
    __shared__ float tile[32][33];
    const int h  = blockIdx.z;
    const int k0 = blockIdx.x * 32;
    const int n0 = blockIdx.y * 32;
    const int tx = threadIdx.x, ty = threadIdx.y;
    const float* ph = in + (long)h * K * N;

    #pragma unroll
    for (int j = 0; j < 32; j += 8)
        tile[ty + j][tx] = ph[(long)(k0 + ty + j) * N + n0 + tx];
    __syncthreads();

    const long ob = (long)h * N * K;
    #pragma unroll
    for (int j = 0; j < 32; j += 8) {
        const float v = tile[tx][ty + j];
        const __nv_bfloat16 hv = __float2bfloat16_rn(v);
        const long o = ob + (long)(n0 + ty + j) * K + k0 + tx;
        outh[o] = hv;
        outl[o] = __float2bfloat16_rn(v - __bfloat162float(hv));
    }
}

// ---------------- F=256 attention (round-14 proven) ----------------
__global__ void __launch_bounds__(128, 8)
gat_attn256(const float* __restrict__ xsA, const float* __restrict__ xnA, int SA, int nA,
            const float* __restrict__ xsB, const float* __restrict__ xnB, int SB,
            const float* __restrict__ a_self, const float* __restrict__ a_neigh,
            __nv_bfloat16* __restrict__ yh, __nv_bfloat16* __restrict__ yl)
{
    extern __shared__ float sm[];
    float* sx     = sm;                 // 26*256
    float* slog   = sm + 26 * 256;      // 26*4
    float* slself = slog + 26 * 4;      // 4

    const int tid = threadIdx.x;
    const int w = tid >> 5, l = tid & 31;
    const int item = blockIdx.x;

    const float* xs; const float* xn; int S;
    if (item < nA) { xs = xsA + (long)item * 256;  xn = xnA + (long)item * SA * 256;  S = SA; }
    else           { int b = item - nA;
                     xs = xsB + (long)b * 256;     xn = xnB + (long)b * SB * 256;     S = SB; }

    {
        const uint32_t sx_u = smem_u32(sx);
        const float4* s4 = (const float4*)xs;
        for (int i = tid; i < 64; i += 128) CP16(sx_u + i * 16, s4 + i);
        const float4* n4 = (const float4*)xn;
        for (int i = tid; i < S * 64; i += 128) CP16(sx_u + (64 + i) * 16, n4 + i);
        CP_COMMIT();
    }

    if (w == 0) {
        float sl[4] = {0.f, 0.f, 0.f, 0.f};
        #pragma unroll
        for (int fi = 0; fi < 2; fi++) {
            const int f = l * 4 + fi * 128;
            const float4 xv = *(const float4*)(xs + f);
            #pragma unroll
            for (int h = 0; h < 4; h++) {
                const float4 av = *(const float4*)(a_self + h * 256 + f);
                sl[h] += xv.x * av.x + xv.y * av.y + xv.z * av.z + xv.w * av.w;
            }
        }
        #pragma unroll
        for (int h = 0; h < 4; h++) {
            float v = sl[h];
            #pragma unroll
            for (int o = 16; o; o >>= 1) v += __shfl_down_sync(0xffffffffu, v, o);
            if (l == 0) slself[h] = v;
        }
    }
    CP_WAIT0();
    __syncthreads();

    {
        float4 avn[4][2];
        #pragma unroll
        for (int h = 0; h < 4; h++)
            #pragma unroll
            for (int fi = 0; fi < 2; fi++)
                avn[h][fi] = *(const float4*)(a_neigh + h * 256 + l * 4 + fi * 128);

        {
            float lg[4][4] = {};
            #pragma unroll
            for (int ti = 0; ti < 4; ti++) {
                const int t = w + ti * 4;
                if (t <= S) {
                    const float* row = sx + t * 256;
                    #pragma unroll
                    for (int fi = 0; fi < 2; fi++) {
                        const float4 xv = *(const float4*)(row + l * 4 + fi * 128);
                        #pragma unroll
                        for (int h = 0; h < 4; h++)
                            lg[ti][h] += xv.x * avn[h][fi].x + xv.y * avn[h][fi].y
                                       + xv.z * avn[h][fi].z + xv.w * avn[h][fi].w;
                    }
                }
            }
            #pragma unroll
            for (int ti = 0; ti < 4; ti++) {
                const int t = w + ti * 4;
                #pragma unroll
                for (int h = 0; h < 4; h++) {
                    float v = lg[ti][h];
                    #pragma unroll
                    for (int o = 16; o; o >>= 1) v += __shfl_down_sync(0xffffffffu, v, o);
                    if (l == 0 && t <= S) slog[t * 4 + h] = v;
                }
            }
        }
        {
            float lg[3][4] = {};
            #pragma unroll
            for (int ti = 0; ti < 3; ti++) {
                const int t = w + (ti + 4) * 4;
                if (t <= S) {
                    const float* row = sx + t * 256;
                    #pragma unroll
                    for (int fi = 0; fi < 2; fi++) {
                        const float4 xv = *(const float4*)(row + l * 4 + fi * 128);
                        #pragma unroll
                        for (int h = 0; h < 4; h++)
                            lg[ti][h] += xv.x * avn[h][fi].x + xv.y * avn[h][fi].y
                                       + xv.z * avn[h][fi].z + xv.w * avn[h][fi].w;
                    }
                }
            }
            #pragma unroll
            for (int ti = 0; ti < 3; ti++) {
                const int t = w + (ti + 4) * 4;
                #pragma unroll
                for (int h = 0; h < 4; h++) {
                    float v = lg[ti][h];
                    #pragma unroll
                    for (int o = 16; o; o >>= 1) v += __shfl_down_sync(0xffffffffu, v, o);
                    if (l == 0 && t <= S) slog[t * 4 + h] = v;
                }
            }
        }
    }
    __syncthreads();

    if (tid < 32) {
        const bool act = (l <= S);
        float z[4];
        #pragma unroll
        for (int h = 0; h < 4; h++) {
            float v = act ? (slself[h] + slog[l * 4 + h]) : -1e30f;
            z[h] = (v >= 0.f) ? v : NEG_SLOPE * v;
        }
        #pragma unroll
        for (int h = 0; h < 4; h++) {
            float m = z[h];
            #pragma unroll
            for (int o = 16; o; o >>= 1) m = fmaxf(m, __shfl_xor_sync(0xffffffffu, m, o));
            const float ev = act ? __expf(z[h] - m) : 0.f;
            float s = ev;
            #pragma unroll
            for (int o = 16; o; o >>= 1) s += __shfl_xor_sync(0xffffffffu, s, o);
            if (act) slog[l * 4 + h] = ev / s;
        }
    }
    __syncthreads();

    {
        float2 a0 = make_float2(0.f, 0.f), a1 = make_float2(0.f, 0.f);
        float2 a2 = make_float2(0.f, 0.f), a3 = make_float2(0.f, 0.f);
        const float* col = sx + tid * 2;
        for (int s = 0; s <= S; s++) {
            const float2 xv = *(const float2*)(col + s * 256);
            const float4 at = *(const float4*)(slog + s * 4);
            a0.x += at.x * xv.x; a0.y += at.x * xv.y;
            a1.x += at.y * xv.x; a1.y += at.y * xv.y;
            a2.x += at.z * xv.x; a2.y += at.z * xv.y;
            a3.x += at.w * xv.x; a3.y += at.w * xv.y;
        }
        __nv_bfloat16* yoh = yh + (long)item * 1024 + tid * 2;
        __nv_bfloat16* yol = yl + (long)item * 1024 + tid * 2;
        uint32_t lo;
        uint32_t hi = bfsplit2(a0.x, a0.y, lo);
        *(uint32_t*)(yoh + 0 * 256) = hi; *(uint32_t*)(yol + 0 * 256) = lo;
        hi = bfsplit2(a1.x, a1.y, lo);
        *(uint32_t*)(yoh + 1 * 256) = hi; *(uint32_t*)(yol + 1 * 256) = lo;
        hi = bfsplit2(a2.x, a2.y, lo);
        *(uint32_t*)(yoh + 2 * 256) = hi; *(uint32_t*)(yol + 2 * 256) = lo;
        hi = bfsplit2(a3.x, a3.y, lo);
        *(uint32_t*)(yoh + 3 * 256) = hi; *(uint32_t*)(yol + 3 * 256) = lo;
    }
}

// ---------------- F=512 attention: 128 threads, 8 CTAs/SM (proven) ----------------
__global__ void __launch_bounds__(128, 8)
gat_attn512(const float* __restrict__ xs0, const float* __restrict__ xn0, int S,
            const float* __restrict__ a_self, const float* __restrict__ a_neigh,
            __nv_bfloat16* __restrict__ yh, __nv_bfloat16* __restrict__ yl)
{
    extern __shared__ float sm[];
    float* sx     = sm;                 // 11*512
    float* slog   = sm + 11 * 512;      // 11*4
    float* slself = slog + 11 * 4;      // 4

    const int tid = threadIdx.x;
    const int w = tid >> 5, l = tid & 31;
    const int item = blockIdx.x;

    const float* xs = xs0 + (long)item * 512;
    const float* xn = xn0 + (long)item * S * 512;

    {
        const uint32_t sx_u = smem_u32(sx);
        const float4* s4 = (const float4*)xs;
        for (int i = tid; i < 128; i += 128) CP16(sx_u + i * 16, s4 + i);
        const float4* n4 = (const float4*)xn;
        for (int i = tid; i < S * 128; i += 128) CP16(sx_u + (128 + i) * 16, n4 + i);
        CP_COMMIT();
    }

    if (w == 0) {
        float sl[4] = {0.f, 0.f, 0.f, 0.f};
        #pragma unroll
        for (int c = 0; c < 2; c++) {
            #pragma unroll
            for (int fi = 0; fi < 2; fi++) {
                const int f = c * 256 + l * 4 + fi * 128;
                const float4 xv = *(const float4*)(xs + f);
                #pragma unroll
                for (int h = 0; h < 4; h++) {
                    const float4 av = *(const float4*)(a_self + h * 512 + f);
                    sl[h] += xv.x * av.x + xv.y * av.y + xv.z * av.z + xv.w * av.w;
                }
            }
        }
        #pragma unroll
        for (int h = 0; h < 4; h++) {
            float v = sl[h];
            #pragma unroll
            for (int o = 16; o; o >>= 1) v += __shfl_down_sync(0xffffffffu, v, o);
            if (l == 0) slself[h] = v;
        }
    }
    CP_WAIT0();
    __syncthreads();

    {
        float lg[3][4] = {};
        #pragma unroll
        for (int c = 0; c < 2; c++) {
            float4 avn[4][2];
            #pragma unroll
            for (int h = 0; h < 4; h++)
                #pragma unroll
                for (int fi = 0; fi < 2; fi++)
                    avn[h][fi] = *(const float4*)(a_neigh + h * 512 + c * 256 + l * 4 + fi * 128);
            #pragma unroll
            for (int ti = 0; ti < 3; ti++) {
                const int t = w + ti * 4;
                if (t <= S) {
                    const float* row = sx + t * 512 + c * 256;
                    #pragma unroll
                    for (int fi = 0; fi < 2; fi++) {
                        const float4 xv = *(const float4*)(row + l * 4 + fi * 128);
                        #pragma unroll
                        for (int h = 0; h < 4; h++)
                            lg[ti][h] += xv.x * avn[h][fi].x + xv.y * avn[h][fi].y
                                       + xv.z * avn[h][fi].z + xv.w * avn[h][fi].w;
                    }
                }
            }
        }
        #pragma unroll
        for (int ti = 0; ti < 3; ti++) {
            const int t = w + ti * 4;
            #pragma unroll
            for (int h = 0; h < 4; h++) {
                float v = lg[ti][h];
                #pragma unroll
                for (int o = 16; o; o >>= 1) v += __shfl_down_sync(0xffffffffu, v, o);
                if (l == 0 && t <= S) slog[t * 4 + h] = v;
            }
        }
    }
    __syncthreads();

    if (tid < 32) {
        const bool act = (l <= S);
        float z[4];
        #pragma unroll
        for (int h = 0; h < 4; h++) {
            float v = act ? (slself[h] + slog[l * 4 + h]) : -1e30f;
            z[h] = (v >= 0.f) ? v : NEG_SLOPE * v;
        }
        #pragma unroll
        for (int h = 0; h < 4; h++) {
            float m = z[h];
            #pragma unroll
            for (int o = 16; o; o >>= 1) m = fmaxf(m, __shfl_xor_sync(0xffffffffu, m, o));
            const float ev = act ? __expf(z[h] - m) : 0.f;
            float s = ev;
            #pragma unroll
            for (int o = 16; o; o >>= 1) s += __shfl_xor_sync(0xffffffffu, s, o);
            if (act) slog[l * 4 + h] = ev / s;
        }
    }
    __syncthreads();

    {
        const int fi = tid;               // 0..127 f4-columns
        float4 acc4[4];
        #pragma unroll
        for (int h = 0; h < 4; h++) acc4[h] = make_float4(0.f, 0.f, 0.f, 0.f);
        for (int s = 0; s <= S; s++) {
            const float4 xv = *(const float4*)(sx + s * 512 + fi * 4);
            const float4 at = *(const float4*)(slog + s * 4);
            acc4[0].x += at.x * xv.x; acc4[0].y += at.x * xv.y; acc4[0].z += at.x * xv.z; acc4[0].w += at.x * xv.w;
            acc4[1].x += at.y * xv.x; acc4[1].y += at.y * xv.y; acc4[1].z += at.y * xv.z; acc4[1].w += at.y * xv.w;
            acc4[2].x += at.z * xv.x; acc4[2].y += at.z * xv.y; acc4[2].z += at.z * xv.z; acc4[2].w += at.z * xv.w;
            acc4[3].x += at.w * xv.x; acc4[3].y += at.w * xv.y; acc4[3].z += at.w * xv.z; acc4[3].w += at.w * xv.w;
        }
        __nv_bfloat16* yoh = yh + (long)item * 2048;
        __nv_bfloat16* yol = yl + (long)item * 2048;
        #pragma unroll
        for (int h = 0; h < 4; h++) {
            uint32_t lo01, lo23;
            const uint32_t hi01 = bfsplit2(acc4[h].x, acc4[h].y, lo01);
            const uint32_t hi23 = bfsplit2(acc4[h].z, acc4[h].w, lo23);
            *(uint2*)(yoh + h * 512 + fi * 4) = make_uint2(hi01, hi23);
            *(uint2*)(yol + h * 512 + fi * 4) = make_uint2(lo01, lo23);
        }
    }
}

// ---------------- 8-way partial reduce ----------------
__global__ void reduce8(const float4* __restrict__ p, float4* __restrict__ out, int n4)
{
    const int i = blockIdx.x * blockDim.x + threadIdx.x;
    if (i < n4) {
        float4 s = p[i];
        #pragma unroll
        for (int j = 1; j < 8; j++) {
            const float4 v = p[i + j * n4];
            s.x += v.x; s.y += v.y; s.z += v.z; s.w += v.w;
        }
        out[i] = s;
    }
}

// ---------------- launch ----------------
template <typename T>
static T* sym_addr(const void* symbol)
{
    void* p = nullptr;
    cudaGetSymbolAddress(&p, symbol);
    return (T*)p;
}

extern "C" void kernel_launch(void* const* d_in, const int* in_sizes, int n_in,
                              void* d_out, int out_size)
{
    const float* x0  = (const float*)d_in[0];
    const float* x1  = (const float*)d_in[1];
    const float* x2  = (const float*)d_in[2];
    const float* w0  = (const float*)d_in[3];
    const float* a0s = (const float*)d_in[4];
    const float* a0n = (const float*)d_in[5];
    const float* w1  = (const float*)d_in[6];
    const float* a1s = (const float*)d_in[7];
    const float* a1n = (const float*)d_in[8];
    const float* fcw = (const float*)d_in[9];
    float* out = (float*)d_out;

    const int Bn   = in_sizes[0] / 256;        // 1024
    const int nA   = Bn * 10;                  // 10240
    const int nTot = nA + Bn;                  // 11264

    __nv_bfloat16* yh   = sym_addr<__nv_bfloat16>(g_yh);
    __nv_bfloat16* yl   = sym_addr<__nv_bfloat16>(g_yl);
    float*         hb   = sym_addr<float>(g_h);
    __nv_bfloat16* y2h  = sym_addr<__nv_bfloat16>(g_y2h);
    __nv_bfloat16* y2l  = sym_addr<__nv_bfloat16>(g_y2l);
    __nv_bfloat16* Wt2h = sym_addr<__nv_bfloat16>(g_Wt2h);
    __nv_bfloat16* Wt2l = sym_addr<__nv_bfloat16>(g_Wt2l);
    __nv_bfloat16* Wt0h = sym_addr<__nv_bfloat16>(g_Wt0h);
    __nv_bfloat16* Wt0l = sym_addr<__nv_bfloat16>(g_Wt0l);
    float*         part = sym_addr<float>(g_part);

    const int smemF = STAGE_SHORTS * 2;            // fold: one stage (55296 B)
    const int smemP = STAGE_SHORTS * 2 * 2;        // pre:  two stages (110592 B)
    cudaFuncSetAttribute(gemm_hmma_fold, cudaFuncAttributeMaxDynamicSharedMemorySize, smemF);
    cudaFuncSetAttribute(gemm_hmma_pre, cudaFuncAttributeMaxDynamicSharedMemorySize, smemP);

    const int smemA0 = (26 * 256 + 26 * 4 + 8) * 4;   // ~27.1 KB
    const int smemA1 = (11 * 512 + 11 * 4 + 8) * 4;   // ~22.7 KB
    cudaFuncSetAttribute(gat_attn256, cudaFuncAttributeMaxDynamicSharedMemorySize, smemA0);
    cudaFuncSetAttribute(gat_attn512, cudaFuncAttributeMaxDynamicSharedMemorySize, smemA1);

    // ---- fold: Wt2[h] = (w1[h] @ fcw[h-slice]) transposed+split ----
    gemm_hmma_fold<<<dim3(8, 2, NHEAD), 256, smemF>>>(w1, fcw, Wt2h, Wt2l);

    // ---- w0 transpose+split ----
    transpose_split<<<dim3(8, 4, NHEAD), dim3(32, 8)>>>(w0, Wt0h, Wt0l, 256, 128);

    // ---- layer-0 attention: 128 threads, 8 CTAs/SM ----
    gat_attn256<<<nTot, 128, smemA0>>>(x1, x2, 25, nA,
                                       x0, x1, 10,
                                       a0s, a0n, yh, yl);

    // ---- layer-0 projection: hb = y @ w0 per head  (cp.async pipelined) ----
    gemm_hmma_pre<<<dim3(nTot / 64, 1, NHEAD), 256, smemP>>>(
        yh, yl, Wt0h, Wt0l, hb,
        /*kLen*/256, /*kStride*/256, /*nSplit*/1,
        /*lda*/1024, /*aHead*/256, /*wHead*/(long)128 * 256,
        /*ldc*/512, /*cSeg*/128);

    // ---- layer-1 attention: 128 threads, 8 CTAs/SM ----
    gat_attn512<<<Bn, 128, smemA1>>>(hb + (long)nA * 512, hb, 10,
                                     a1s, a1n, y2h, y2l);

    // ---- folded back-end, split-K x2 (cp.async pipelined) ----
    gemm_hmma_pre<<<dim3(Bn / 64, 2, NHEAD * 2), 256, smemP>>>(
        y2h, y2l, Wt2h, Wt2l, part,
        /*kLen*/256, /*kStride*/512, /*nSplit*/2,
        /*lda*/2048, /*aHead*/512, /*wHead*/(long)256 * 512,
        /*ldc*/256, /*cSeg*/(long)Bn * 256);

    // ---- out = sum over 8 partials ----
    const int n4 = Bn * 256 / 4;
    reduce8<<<(n4 + 255) / 256, 256>>>((const float4*)part, (float4*)out, n4);
}